// round 7
// baseline (speedup 1.0000x reference)
#include <cuda_runtime.h>
#include <cuda_bf16.h>
#include <cuda_fp16.h>
#include <math.h>
#include <stdint.h>

#define BB 128     // batch
#define DD 512     // hidden
#define GG 2048    // 4*D
#define VV 10000   // vocab
#define TT 20      // timesteps
#define NCTA 128   // persistent kernel CTAs

// ---------------- device scratch (no allocation allowed) ----------------
__device__ float g_bias0[GG];
__device__ float g_bias0f[GG];
__device__ float g_bias1[GG];
__device__ unsigned g_bar;
// bf16 operands for the two big GEMMs
__device__ __nv_bfloat16 g_B1hi[(size_t)DD * VV];  // W_enc^T rows=512, K=10000
__device__ __nv_bfloat16 g_B1lo[(size_t)DD * VV];
__device__ __nv_bfloat16 g_B2hi[(size_t)VV * DD];  // W_enc rows=10000, K=512
__device__ __nv_bfloat16 g_B2lo[(size_t)VV * DD];
__device__ __nv_bfloat16 g_H1hi[TT * BB * DD];     // h1 history for GEMM2 (bf16 hi/lo)
__device__ __nv_bfloat16 g_H1lo[TT * BB * DD];
// fp16 recurrence state
__device__ __half g_H1f[TT * BB * DD];             // h1 history (fp16, cell input)
__device__ __half g_h0fA[BB * DD], g_h0fB[BB * DD];
__device__ __half g_h1zf[BB * DD];
// fused, gate-interleaved cell weights (fp16 hi/lo): rows n'=d*4+gate, K=1024=[x|h]
__device__ __half g_Wc0hi[(size_t)GG * 1024];
__device__ __half g_Wc0lo[(size_t)GG * 1024];
__device__ __half g_Wc1hi[(size_t)GG * 1024];
__device__ __half g_Wc1lo[(size_t)GG * 1024];

// =========================================================================
// helpers
// =========================================================================
__device__ __forceinline__ uint32_t smem_u32(const void* p) {
    uint32_t a;
    asm("{ .reg .u64 t; cvta.to.shared.u64 t, %1; cvt.u32.u64 %0, t; }" : "=r"(a) : "l"(p));
    return a;
}
#define SWZ128(o) ((o) ^ (((o) >> 3) & 0x70))

__device__ __forceinline__ void ldsm_x4(uint32_t* r, uint32_t addr) {
    asm volatile("ldmatrix.sync.aligned.m8n8.x4.shared.b16 {%0,%1,%2,%3}, [%4];"
                 : "=r"(r[0]), "=r"(r[1]), "=r"(r[2]), "=r"(r[3]) : "r"(addr));
}
__device__ __forceinline__ void mma16816(float* d, const uint32_t* a, const uint32_t* b) {
    asm volatile(
        "mma.sync.aligned.m16n8k16.row.col.f32.bf16.bf16.f32 "
        "{%0,%1,%2,%3}, {%4,%5,%6,%7}, {%8,%9}, {%0,%1,%2,%3};"
        : "+f"(d[0]), "+f"(d[1]), "+f"(d[2]), "+f"(d[3])
        : "r"(a[0]), "r"(a[1]), "r"(a[2]), "r"(a[3]), "r"(b[0]), "r"(b[1]));
}
__device__ __forceinline__ void mma16816h(float* d, const uint32_t* a, const uint32_t* b) {
    asm volatile(
        "mma.sync.aligned.m16n8k16.row.col.f32.f16.f16.f32 "
        "{%0,%1,%2,%3}, {%4,%5,%6,%7}, {%8,%9}, {%0,%1,%2,%3};"
        : "+f"(d[0]), "+f"(d[1]), "+f"(d[2]), "+f"(d[3])
        : "r"(a[0]), "r"(a[1]), "r"(a[2]), "r"(a[3]), "r"(b[0]), "r"(b[1]));
}
__device__ __forceinline__ void cp_async16(uint32_t daddr, const void* g, unsigned sz) {
    asm volatile("cp.async.cg.shared.global [%0], [%1], 16, %2;"
                 :: "r"(daddr), "l"(g), "r"(sz));
}
#define CP_COMMIT() asm volatile("cp.async.commit_group;" ::: "memory")
#define CP_WAIT(n)  asm volatile("cp.async.wait_group %0;" :: "n"(n) : "memory")

// =========================================================================
// prep kernels
// =========================================================================
__global__ void zero_state_kernel() {
    int i = blockIdx.x * blockDim.x + threadIdx.x;
    if (i == 0) g_bar = 0u;
    if (i < BB * DD) g_h1zf[i] = __float2half_rn(0.f);
}

__global__ void bias_prep_kernel(const float* __restrict__ b_ih0, const float* __restrict__ b_hh0,
                                 const float* __restrict__ b_ih1, const float* __restrict__ b_hh1) {
    int g = blockIdx.x * blockDim.x + threadIdx.x;
    if (g < GG) {
        g_bias0[g] = b_ih0[g] + b_hh0[g];
        g_bias1[g] = b_ih1[g] + b_hh1[g];
    }
}

__global__ void bfused_kernel(const float* __restrict__ W_ih0, const float* __restrict__ b_enc) {
    __shared__ float red[256];
    int g = blockIdx.x;
    float s = 0.f;
    for (int v = threadIdx.x; v < VV; v += 256)
        s += W_ih0[(size_t)g * VV + v] * b_enc[v];
    red[threadIdx.x] = s;
    __syncthreads();
    for (int o = 128; o > 0; o >>= 1) {
        if (threadIdx.x < o) red[threadIdx.x] += red[threadIdx.x + o];
        __syncthreads();
    }
    if (threadIdx.x == 0) g_bias0f[g] = g_bias0[g] + red[0];
}

// W_enc (10000,512) fp32 -> B1hi/B1lo (512,10000) bf16 (fused transpose + split)
__global__ void transpose_split_kernel(const float* __restrict__ src,
                                       __nv_bfloat16* __restrict__ hi,
                                       __nv_bfloat16* __restrict__ lo) {
    __shared__ float tile[32][33];
    int c0 = blockIdx.x * 32;      // over 512 (cols of src)
    int r0 = blockIdx.y * 32;      // over 10000 (rows of src)
    int c = c0 + threadIdx.x;
    for (int i = threadIdx.y; i < 32; i += 8) {
        int r = r0 + i;
        if (r < VV) tile[i][threadIdx.x] = src[(size_t)r * DD + c];
    }
    __syncthreads();
    int r = r0 + threadIdx.x;      // dst col
    if (r < VV) {
        for (int i = threadIdx.y; i < 32; i += 8) {
            float v = tile[threadIdx.x][i];
            __nv_bfloat16 h = __float2bfloat16_rn(v);
            hi[(size_t)(c0 + i) * VV + r] = h;
            lo[(size_t)(c0 + i) * VV + r] = __float2bfloat16_rn(v - __bfloat162float(h));
        }
    }
}

// fp32 -> (bf16 hi, bf16 lo).  n divisible by 4.
__global__ void split_bf16_kernel(const float* __restrict__ src,
                                  __nv_bfloat16* __restrict__ hi,
                                  __nv_bfloat16* __restrict__ lo, int n) {
    int i = (blockIdx.x * blockDim.x + threadIdx.x) * 4;
    if (i < n) {
        float4 v = *(const float4*)(src + i);
        float vv[4] = {v.x, v.y, v.z, v.w};
        __nv_bfloat16 h[4], l[4];
        #pragma unroll
        for (int j = 0; j < 4; j++) {
            h[j] = __float2bfloat16_rn(vv[j]);
            l[j] = __float2bfloat16_rn(vv[j] - __bfloat162float(h[j]));
        }
        *(uint2*)(hi + i) = *(uint2*)h;
        *(uint2*)(lo + i) = *(uint2*)l;
    }
}

__global__ void f32_to_f16_kernel(const float* __restrict__ src, __half* __restrict__ dst, int n) {
    int i = (blockIdx.x * blockDim.x + threadIdx.x) * 4;
    if (i < n) {
        float4 v = *(const float4*)(src + i);
        __half h[4] = {__float2half_rn(v.x), __float2half_rn(v.y),
                       __float2half_rn(v.z), __float2half_rn(v.w)};
        *(uint2*)(dst + i) = *(uint2*)h;
    }
}

// layer-0 h-part: W_hh0 (2048,512) -> Wc0 fp16 hi/lo at k in [512,1024). grid 2048 x 128.
__global__ void build_cell_wh_kernel(const float* __restrict__ srcH,
                                     __half* __restrict__ whi, __half* __restrict__ wlo) {
    int idx = blockIdx.x * 128 + threadIdx.x;
    int e = idx * 4;
    int np = e >> 9, k4 = e & 511;
    int d = np >> 2, gate = np & 3;
    int n = gate * 512 + d;
    float4 v = *(const float4*)(srcH + (size_t)n * 512 + k4);
    float vv[4] = {v.x, v.y, v.z, v.w};
    __half h[4], l[4];
    #pragma unroll
    for (int j = 0; j < 4; j++) {
        h[j] = __float2half_rn(vv[j]);
        l[j] = __float2half_rn(vv[j] - __half2float(h[j]));
    }
    *(uint2*)(whi + (size_t)np * 1024 + 512 + k4) = *(uint2*)h;
    *(uint2*)(wlo + (size_t)np * 1024 + 512 + k4) = *(uint2*)l;
}

// layer-1 full: [W_ih1 | W_hh1] -> Wc1 fp16 hi/lo. grid 2048 x 256.
__global__ void build_cell_w_kernel(const float* __restrict__ srcX, const float* __restrict__ srcH,
                                    __half* __restrict__ whi, __half* __restrict__ wlo) {
    int idx = blockIdx.x * 256 + threadIdx.x;
    int e = idx * 4;
    int np = e >> 10, k4 = e & 1023;
    int d = np >> 2, gate = np & 3;
    int n = gate * 512 + d;
    const float* s = (k4 < 512) ? (srcX + (size_t)n * 512 + k4)
                                : (srcH + (size_t)n * 512 + (k4 - 512));
    float4 v = *(const float4*)s;
    float vv[4] = {v.x, v.y, v.z, v.w};
    __half h[4], l[4];
    #pragma unroll
    for (int j = 0; j < 4; j++) {
        h[j] = __float2half_rn(vv[j]);
        l[j] = __float2half_rn(vv[j] - __half2float(h[j]));
    }
    *(uint2*)(whi + (size_t)np * 1024 + k4) = *(uint2*)h;
    *(uint2*)(wlo + (size_t)np * 1024 + k4) = *(uint2*)l;
}

// =========================================================================
// GEMM1 (fused): Wc0[k<512] = split_f16( W_ih0(2048,10000)fp32 @ B1(512,10000)^T )
// A read as fp32, converted to bf16 hi/lo in-kernel (LDG->reg->STS pipeline).
// BM=64, BN=128, BK=64; 8 warps (4m x 2n); grid (4, 32).
// smem/buf: Ahi 8K | Alo 8K | Bhi 16K | Blo 16K = 48K; x2 = 96K
// =========================================================================
#define G1_BUF 49152
#define G1_SMEM (2 * G1_BUF)

__global__ __launch_bounds__(256) void gemm1_fused_kernel(
    const float* __restrict__ A,
    const __nv_bfloat16* __restrict__ Bhi, const __nv_bfloat16* __restrict__ Blo,
    __half* __restrict__ Whi, __half* __restrict__ Wlo)
{
    extern __shared__ char smem[];
    const uint32_t sb = smem_u32(smem);
    const int tid = threadIdx.x, wid = tid >> 5, lane = tid & 31;
    const int wm = wid & 3, wn = wid >> 2;
    const int m0 = blockIdx.y * 64, n0 = blockIdx.x * 128;
    const int NT = (VV + 63) / 64;   // 157

    float acc[8][4];
    #pragma unroll
    for (int nt = 0; nt < 8; nt++)
        #pragma unroll
        for (int j = 0; j < 4; j++) acc[nt][j] = 0.f;

    float4 areg[4];

    auto ldgA = [&](int kt) {
        const int kc = kt * 64;
        #pragma unroll
        for (int it = 0; it < 4; it++) {
            int i = it * 256 + tid;
            int r = i >> 4, c4 = i & 15;
            int gk = kc + c4 * 4;
            areg[it] = (gk < VV) ? *(const float4*)(A + (size_t)(m0 + r) * VV + gk)
                                 : make_float4(0.f, 0.f, 0.f, 0.f);
        }
    };
    auto stsA = [&](int buf) {
        const uint32_t bhi = sb + buf * G1_BUF;
        const uint32_t blo = bhi + 8192;
        #pragma unroll
        for (int it = 0; it < 4; it++) {
            int i = it * 256 + tid;
            int r = i >> 4, c4 = i & 15;
            float vv[4] = {areg[it].x, areg[it].y, areg[it].z, areg[it].w};
            __nv_bfloat16 h[4], l[4];
            #pragma unroll
            for (int j = 0; j < 4; j++) {
                h[j] = __float2bfloat16_rn(vv[j]);
                l[j] = __float2bfloat16_rn(vv[j] - __bfloat162float(h[j]));
            }
            uint32_t off = SWZ128(r * 128 + c4 * 8);
            *(uint2*)(smem + buf * G1_BUF + off) = *(uint2*)h;
            *(uint2*)(smem + buf * G1_BUF + 8192 + off) = *(uint2*)l;
        }
    };
    auto cpB = [&](int kt, int buf) {
        const int kc = kt * 64;
        const uint32_t bufb = sb + buf * G1_BUF + 16384;
        #pragma unroll
        for (int w = 0; w < 2; w++) {
            const __nv_bfloat16* src = w ? Blo : Bhi;
            uint32_t tdst = bufb + w * 16384;
            #pragma unroll
            for (int it = 0; it < 4; it++) {
                int i = it * 256 + tid;
                int r = i >> 3, c16 = i & 7;
                int gk = kc + c16 * 8;
                bool inb = gk < VV;
                cp_async16(tdst + SWZ128(r * 128 + c16 * 16),
                           src + (inb ? ((size_t)(n0 + r) * VV + gk) : 0), inb ? 16u : 0u);
            }
        }
        CP_COMMIT();
    };

    // prologue
    ldgA(0);
    cpB(0, 0);
    stsA(0);
    const int g8 = lane >> 3, rg = lane & 7;

    for (int kt = 0; kt < NT; kt++) {
        const int buf = kt & 1;
        if (kt + 1 < NT) {
            ldgA(kt + 1);
            cpB(kt + 1, buf ^ 1);
            CP_WAIT(1);
        } else {
            CP_WAIT(0);
        }
        __syncthreads();

        const uint32_t bAh = sb + buf * G1_BUF;
        const uint32_t bAl = bAh + 8192;
        const uint32_t bBh = bAh + 16384;
        const uint32_t bBl = bAh + 32768;

        #pragma unroll
        for (int kk = 0; kk < 4; kk++) {
            const int kb = kk * 32;
            uint32_t ah[4], al[4], bh[8][2], bl[8][2];
            {
                int row = wm * 16 + (g8 & 1) * 8 + rg;
                uint32_t off = SWZ128(row * 128 + kb + (g8 >> 1) * 16);
                ldsm_x4(ah, bAh + off);
                ldsm_x4(al, bAl + off);
            }
            #pragma unroll
            for (int p = 0; p < 4; p++) {
                int rowb = wn * 64 + p * 16 + (g8 >> 1) * 8 + rg;
                uint32_t off = SWZ128(rowb * 128 + kb + (g8 & 1) * 16);
                uint32_t t[4];
                ldsm_x4(t, bBh + off);
                bh[2 * p][0] = t[0]; bh[2 * p][1] = t[1];
                bh[2 * p + 1][0] = t[2]; bh[2 * p + 1][1] = t[3];
                ldsm_x4(t, bBl + off);
                bl[2 * p][0] = t[0]; bl[2 * p][1] = t[1];
                bl[2 * p + 1][0] = t[2]; bl[2 * p + 1][1] = t[3];
            }
            #pragma unroll
            for (int nt = 0; nt < 8; nt++) {
                mma16816(acc[nt], ah, bh[nt]);
                mma16816(acc[nt], ah, bl[nt]);
                mma16816(acc[nt], al, bh[nt]);
            }
        }

        if (kt + 1 < NT) stsA(buf ^ 1);
        __syncthreads();
    }

    // epilogue: gate-interleaved fp16 hi/lo into Wc0 (k<512)
    #pragma unroll
    for (int rr = 0; rr < 2; rr++) {
        int row = m0 + wm * 16 + (lane >> 2) + rr * 8;
        int np = (row & 511) * 4 + (row >> 9);
        #pragma unroll
        for (int nt = 0; nt < 8; nt++) {
            int col = n0 + wn * 64 + nt * 8 + (lane & 3) * 2;
            float v0 = acc[nt][2 * rr + 0];
            float v1 = acc[nt][2 * rr + 1];
            __half h0 = __float2half_rn(v0), h1 = __float2half_rn(v1);
            __half l0 = __float2half_rn(v0 - __half2float(h0));
            __half l1 = __float2half_rn(v1 - __half2float(h1));
            __half hh[2] = {h0, h1}, ll[2] = {l0, l1};
            *(uint32_t*)(Whi + (size_t)np * 1024 + col) = *(uint32_t*)hh;
            *(uint32_t*)(Wlo + (size_t)np * 1024 + col) = *(uint32_t*)ll;
        }
    }
}

// =========================================================================
// GEMM2 (bf16x3): OUT(M,N) = A(M,K)@B(N,K)^T + bias.  BM=256, BN=128, BK=64.
// 16 warps (8m x 2n), 512 threads.
// =========================================================================
template<int MT, int MW>
__global__ __launch_bounds__(MW * 64) void gemm_bf16x3_kernel(
    const __nv_bfloat16* __restrict__ Ahi, const __nv_bfloat16* __restrict__ Alo,
    const __nv_bfloat16* __restrict__ Bhi, const __nv_bfloat16* __restrict__ Blo,
    float* __restrict__ C, const float* __restrict__ bias,
    int Mtot, int Ntot, int Ktot)
{
    constexpr int BM = MW * MT * 16;
    constexpr int NTH = MW * 64;
    constexpr int ABYTES = BM * 128;
    constexpr int BUFBYTES = 2 * ABYTES + 32768;
    extern __shared__ char smem[];
    const uint32_t sb = smem_u32(smem);
    const int tid = threadIdx.x, wid = tid >> 5, lane = tid & 31;
    const int wm = wid % MW, wn = wid / MW;
    const int m0 = blockIdx.y * BM, n0 = blockIdx.x * 128;
    const int NT = (Ktot + 63) / 64;

    float acc[MT][8][4];
    #pragma unroll
    for (int mt = 0; mt < MT; mt++)
        #pragma unroll
        for (int nt = 0; nt < 8; nt++)
            #pragma unroll
            for (int j = 0; j < 4; j++) acc[mt][nt][j] = 0.f;

    auto load_chunk = [&](int kt, int buf) {
        const int kc = kt * 64;
        const uint32_t bufbase = sb + buf * BUFBYTES;
        #pragma unroll
        for (int w = 0; w < 2; w++) {
            const __nv_bfloat16* src = w ? Alo : Ahi;
            uint32_t tdst = bufbase + w * ABYTES;
            for (int i = tid; i < BM * 8; i += NTH) {
                int r = i >> 3, c16 = i & 7;
                int gr = m0 + r, gk = kc + c16 * 8;
                bool inb = (gr < Mtot) && (gk < Ktot);
                cp_async16(tdst + SWZ128(r * 128 + c16 * 16),
                           src + (inb ? ((size_t)gr * Ktot + gk) : 0), inb ? 16u : 0u);
            }
        }
        #pragma unroll
        for (int w = 0; w < 2; w++) {
            const __nv_bfloat16* src = w ? Blo : Bhi;
            uint32_t tdst = bufbase + 2 * ABYTES + w * 16384;
            for (int i = tid; i < 1024; i += NTH) {
                int r = i >> 3, c16 = i & 7;
                int gr = n0 + r, gk = kc + c16 * 8;
                bool inb = (gr < Ntot) && (gk < Ktot);
                cp_async16(tdst + SWZ128(r * 128 + c16 * 16),
                           src + (inb ? ((size_t)gr * Ktot + gk) : 0), inb ? 16u : 0u);
            }
        }
        CP_COMMIT();
    };

    load_chunk(0, 0);
    const int g8 = lane >> 3, rg = lane & 7;

    for (int kt = 0; kt < NT; kt++) {
        const int buf = kt & 1;
        if (kt + 1 < NT) { load_chunk(kt + 1, buf ^ 1); CP_WAIT(1); }
        else             { CP_WAIT(0); }
        __syncthreads();

        const uint32_t bAh = sb + buf * BUFBYTES;
        const uint32_t bAl = bAh + ABYTES;
        const uint32_t bBh = bAh + 2 * ABYTES;
        const uint32_t bBl = bBh + 16384;

        #pragma unroll
        for (int kk = 0; kk < 4; kk++) {
            const int kb = kk * 32;
            uint32_t ah[MT][4], al[MT][4], bh[8][2], bl[8][2];
            #pragma unroll
            for (int mt = 0; mt < MT; mt++) {
                int row = wm * (16 * MT) + mt * 16 + (g8 & 1) * 8 + rg;
                uint32_t off = SWZ128(row * 128 + kb + (g8 >> 1) * 16);
                ldsm_x4(ah[mt], bAh + off);
                ldsm_x4(al[mt], bAl + off);
            }
            #pragma unroll
            for (int p = 0; p < 4; p++) {
                int rowb = wn * 64 + p * 16 + (g8 >> 1) * 8 + rg;
                uint32_t off = SWZ128(rowb * 128 + kb + (g8 & 1) * 16);
                uint32_t t[4];
                ldsm_x4(t, bBh + off);
                bh[2 * p][0] = t[0]; bh[2 * p][1] = t[1];
                bh[2 * p + 1][0] = t[2]; bh[2 * p + 1][1] = t[3];
                ldsm_x4(t, bBl + off);
                bl[2 * p][0] = t[0]; bl[2 * p][1] = t[1];
                bl[2 * p + 1][0] = t[2]; bl[2 * p + 1][1] = t[3];
            }
            #pragma unroll
            for (int mt = 0; mt < MT; mt++)
                #pragma unroll
                for (int nt = 0; nt < 8; nt++) {
                    mma16816(acc[mt][nt], ah[mt], bh[nt]);
                    mma16816(acc[mt][nt], ah[mt], bl[nt]);
                    mma16816(acc[mt][nt], al[mt], bh[nt]);
                }
        }
        __syncthreads();
    }

    #pragma unroll
    for (int mt = 0; mt < MT; mt++) {
        int row = m0 + wm * (16 * MT) + mt * 16 + (lane >> 2);
        #pragma unroll
        for (int nt = 0; nt < 8; nt++) {
            int col = n0 + wn * 64 + nt * 8 + (lane & 3) * 2;
            if (col < Ntot) {
                float b0 = 0.f, b1 = 0.f;
                if (bias) { b0 = bias[col]; b1 = bias[col + 1]; }
                float2 v0 = make_float2(acc[mt][nt][0] + b0, acc[mt][nt][1] + b1);
                float2 v1 = make_float2(acc[mt][nt][2] + b0, acc[mt][nt][3] + b1);
                *(float2*)&C[(size_t)row * Ntot + col] = v0;
                *(float2*)&C[(size_t)(row + 8) * Ntot + col] = v1;
            }
        }
    }
}

// =========================================================================
// persistent LSTM recurrence, fp16 2-term (A fp16 single, W fp16 hi/lo).
// 128 CTAs x 256 threads; CTA b owns gate rows n0 = b*16 (d in [b*4,b*4+4)).
// smem: W0 64K | W1 64K | A dbuf 32K | gates 8K = 168K
// =========================================================================
#define PSM_W0 0
#define PSM_W1 65536
#define PSM_A  131072
#define PSM_G  163840
#define PERS_SMEM 172032

__global__ __launch_bounds__(256) void lstm_persistent_kernel(
    const __half* __restrict__ Wc0hi, const __half* __restrict__ Wc0lo,
    const __half* __restrict__ Wc1hi, const __half* __restrict__ Wc1lo,
    __half* __restrict__ h0fA, __half* __restrict__ h0fB,
    const __half* __restrict__ h1zf, __half* __restrict__ H1f,
    __nv_bfloat16* __restrict__ H1hi, __nv_bfloat16* __restrict__ H1lo,
    const float* __restrict__ bias0, const float* __restrict__ bias0f,
    const float* __restrict__ bias1)
{
    extern __shared__ char smem[];
    const uint32_t sb = smem_u32(smem);
    float* gates = (float*)(smem + PSM_G);
    const int tid = threadIdx.x, wid = tid >> 5, lane = tid & 31;
    const int n0 = blockIdx.x * 16;
    const int g8 = lane >> 3, rg = lane & 7;

    // persistent weight slices (both layers, hi+lo)
    {
        const __half* srcs[4] = {Wc0hi, Wc0lo, Wc1hi, Wc1lo};
        const uint32_t dsts[4] = {PSM_W0, PSM_W0 + 32768, PSM_W1, PSM_W1 + 32768};
        #pragma unroll
        for (int w = 0; w < 4; w++) {
            const __half* src = srcs[w];
            #pragma unroll
            for (int it = 0; it < 8; it++) {
                int i = it * 256 + tid;
                int ch = i >> 7, r = (i >> 3) & 15, c16 = i & 7;
                cp_async16(sb + dsts[w] + ch * 2048 + SWZ128(r * 128 + c16 * 16),
                           src + (size_t)(n0 + r) * 1024 + ch * 64 + c16 * 8, 16);
            }
        }
        CP_COMMIT();
    }

    float rb0[2][4], rb0f[2][4], rb1[2][4];
    #pragma unroll
    for (int it = 0; it < 2; it++) {
        int idx = it * 256 + tid;
        int dd = idx & 3;
        int d = blockIdx.x * 4 + dd;
        #pragma unroll
        for (int gte = 0; gte < 4; gte++) {
            rb0[it][gte]  = bias0[gte * 512 + d];
            rb0f[it][gte] = bias0f[gte * 512 + d];
            rb1[it][gte]  = bias1[gte * 512 + d];
        }
    }

    float c0r[2] = {0.f, 0.f}, c1r[2] = {0.f, 0.f};
    unsigned epoch = 0;
    int cur = 0;

    for (int t = 0; t < TT; t++) {
        #pragma unroll
        for (int layer = 0; layer < 2; layer++) {
            const __half *xf, *hf;
            int kstart;
            if (layer == 0) {
                kstart = (t == 0) ? 8 : 0;
                xf = (t == 0) ? (const __half*)0 : H1f + (size_t)(t - 1) * BB * DD;
                hf = cur ? h0fB : h0fA;
            } else {
                kstart = 0;
                xf = cur ? h0fA : h0fB;     // newly written h0
                hf = (t == 0) ? h1zf : H1f + (size_t)(t - 1) * BB * DD;
            }
            const uint32_t wbase = sb + (layer ? PSM_W1 : PSM_W0);

            auto load_chunk = [&](int ch, int buf) {
                const __half* src = (ch < 8) ? xf : hf;
                int koff = (ch & 7) * 64;
                const uint32_t base = sb + PSM_A + buf * 16384;
                #pragma unroll
                for (int it = 0; it < 4; it++) {
                    int i = it * 256 + tid;
                    int r = i >> 3, c16 = i & 7;
                    cp_async16(base + SWZ128(r * 128 + c16 * 16),
                               src + (size_t)r * 512 + koff + c16 * 8, 16);
                }
                CP_COMMIT();
            };

            float acc[2][4];
            #pragma unroll
            for (int b = 0; b < 2; b++)
                #pragma unroll
                for (int j = 0; j < 4; j++) acc[b][j] = 0.f;

            load_chunk(kstart, 0);
            for (int ch = kstart; ch < 16; ch++) {
                const int buf = (ch - kstart) & 1;
                if (ch + 1 < 16) { load_chunk(ch + 1, buf ^ 1); CP_WAIT(1); }
                else             { CP_WAIT(0); }
                __syncthreads();

                const uint32_t bA = sb + PSM_A + buf * 16384;
                const uint32_t bW = wbase + ch * 2048;
                const uint32_t bWl = bW + 32768;

                #pragma unroll
                for (int kk = 0; kk < 4; kk++) {
                    const int kb = kk * 32;
                    uint32_t a4[4], tw[4], twl[4];
                    int row = wid * 16 + (g8 & 1) * 8 + rg;
                    ldsm_x4(a4, bA + SWZ128(row * 128 + kb + (g8 >> 1) * 16));
                    int rowb = (g8 >> 1) * 8 + rg;
                    uint32_t offB = SWZ128(rowb * 128 + kb + (g8 & 1) * 16);
                    ldsm_x4(tw, bW + offB);
                    ldsm_x4(twl, bWl + offB);
                    uint32_t bh0[2] = {tw[0], tw[1]},  bh1[2] = {tw[2], tw[3]};
                    uint32_t bl0[2] = {twl[0], twl[1]}, bl1[2] = {twl[2], twl[3]};
                    mma16816h(acc[0], a4, bh0);
                    mma16816h(acc[0], a4, bl0);
                    mma16816h(acc[1], a4, bh1);
                    mma16816h(acc[1], a4, bl1);
                }
                __syncthreads();
            }

            {
                int r0 = wid * 16 + (lane >> 2);
                int cb = (lane & 3) * 2;
                #pragma unroll
                for (int b = 0; b < 2; b++) {
                    gates[r0 * 16 + b * 8 + cb]           = acc[b][0];
                    gates[r0 * 16 + b * 8 + cb + 1]       = acc[b][1];
                    gates[(r0 + 8) * 16 + b * 8 + cb]     = acc[b][2];
                    gates[(r0 + 8) * 16 + b * 8 + cb + 1] = acc[b][3];
                }
            }
            __syncthreads();

            __half* of0 = cur ? h0fA : h0fB;
            __half* of1 = H1f + (size_t)t * BB * DD;
            __nv_bfloat16* ohh = H1hi + (size_t)t * BB * DD;
            __nv_bfloat16* ohl = H1lo + (size_t)t * BB * DD;
            #pragma unroll
            for (int it = 0; it < 2; it++) {
                int idx = it * 256 + tid;
                int row = idx >> 2, dd = idx & 3;
                int d = blockIdx.x * 4 + dd;
                const float* rb = (layer == 0) ? ((t == 0) ? rb0[it] : rb0f[it]) : rb1[it];
                float gi = gates[row * 16 + dd * 4 + 0] + rb[0];
                float gf = gates[row * 16 + dd * 4 + 1] + rb[1];
                float gg = gates[row * 16 + dd * 4 + 2] + rb[2];
                float go = gates[row * 16 + dd * 4 + 3] + rb[3];
                float i_ = 1.f / (1.f + expf(-gi));
                float f_ = 1.f / (1.f + expf(-gf));
                float g_ = tanhf(gg);
                float o_ = 1.f / (1.f + expf(-go));
                float* cr = (layer == 0) ? &c0r[it] : &c1r[it];
                float cn = f_ * (*cr) + i_ * g_;
                *cr = cn;
                float hv = o_ * tanhf(cn);
                if (layer == 0) {
                    of0[row * 512 + d] = __float2half_rn(hv);
                } else {
                    of1[row * 512 + d] = __float2half_rn(hv);
                    __nv_bfloat16 hb = __float2bfloat16_rn(hv);
                    ohh[row * 512 + d] = hb;
                    ohl[row * 512 + d] = __float2bfloat16_rn(hv - __bfloat162float(hb));
                }
            }

            __threadfence();
            __syncthreads();
            epoch++;
            if (tid == 0) {
                atomicAdd(&g_bar, 1u);
                unsigned target = epoch * NCTA;
                volatile unsigned* p = &g_bar;
                while (*p < target) { }
                __threadfence();
            }
            __syncthreads();
        }
        cur ^= 1;
    }
}

// =========================================================================
// host
// =========================================================================
extern "C" void kernel_launch(void* const* d_in, const int* in_sizes, int n_in,
                              void* d_out, int out_size) {
    const float* input_ = (const float*)d_in[0];
    const float* W_ih0  = (const float*)d_in[1];
    const float* W_hh0  = (const float*)d_in[2];
    const float* b_ih0  = (const float*)d_in[3];
    const float* b_hh0  = (const float*)d_in[4];
    const float* W_ih1  = (const float*)d_in[5];
    const float* W_hh1  = (const float*)d_in[6];
    const float* b_ih1  = (const float*)d_in[7];
    const float* b_hh1  = (const float*)d_in[8];
    const float* W_enc  = (const float*)d_in[9];
    const float* b_enc  = (const float*)d_in[10];
    float* out = (float*)d_out;

    float *p_bias0, *p_bias0f, *p_bias1;
    __nv_bfloat16 *p_B1hi, *p_B1lo, *p_B2hi, *p_B2lo, *p_H1hi, *p_H1lo;
    __half *p_H1f, *p_h0fA, *p_h0fB, *p_h1zf;
    __half *p_Wc0hi, *p_Wc0lo, *p_Wc1hi, *p_Wc1lo;
    cudaGetSymbolAddress((void**)&p_bias0,  g_bias0);
    cudaGetSymbolAddress((void**)&p_bias0f, g_bias0f);
    cudaGetSymbolAddress((void**)&p_bias1,  g_bias1);
    cudaGetSymbolAddress((void**)&p_B1hi,   g_B1hi);
    cudaGetSymbolAddress((void**)&p_B1lo,   g_B1lo);
    cudaGetSymbolAddress((void**)&p_B2hi,   g_B2hi);
    cudaGetSymbolAddress((void**)&p_B2lo,   g_B2lo);
    cudaGetSymbolAddress((void**)&p_H1hi,   g_H1hi);
    cudaGetSymbolAddress((void**)&p_H1lo,   g_H1lo);
    cudaGetSymbolAddress((void**)&p_H1f,    g_H1f);
    cudaGetSymbolAddress((void**)&p_h0fA,   g_h0fA);
    cudaGetSymbolAddress((void**)&p_h0fB,   g_h0fB);
    cudaGetSymbolAddress((void**)&p_h1zf,   g_h1zf);
    cudaGetSymbolAddress((void**)&p_Wc0hi,  g_Wc0hi);
    cudaGetSymbolAddress((void**)&p_Wc0lo,  g_Wc0lo);
    cudaGetSymbolAddress((void**)&p_Wc1hi,  g_Wc1hi);
    cudaGetSymbolAddress((void**)&p_Wc1lo,  g_Wc1lo);

    cudaFuncSetAttribute((const void*)gemm1_fused_kernel,
                         cudaFuncAttributeMaxDynamicSharedMemorySize, G1_SMEM);
    cudaFuncSetAttribute((const void*)gemm_bf16x3_kernel<2, 8>,
                         cudaFuncAttributeMaxDynamicSharedMemorySize, 196608);
    cudaFuncSetAttribute((const void*)lstm_persistent_kernel,
                         cudaFuncAttributeMaxDynamicSharedMemorySize, PERS_SMEM);

    // ---- prep ----
    zero_state_kernel<<<(BB * DD + 255) / 256, 256>>>();
    bias_prep_kernel<<<(GG + 255) / 256, 256>>>(b_ih0, b_hh0, b_ih1, b_hh1);
    bfused_kernel<<<GG, 256>>>(W_ih0, b_enc);

    dim3 tb(32, 8);
    transpose_split_kernel<<<dim3(DD / 32, (VV + 31) / 32), tb>>>(W_enc, p_B1hi, p_B1lo);
    split_bf16_kernel<<<(VV * DD / 4 + 255) / 256, 256>>>(W_enc, p_B2hi, p_B2lo, VV * DD);
    f32_to_f16_kernel<<<(BB * DD / 4 + 255) / 256, 256>>>(input_, p_h0fA, BB * DD);

    // GEMM1 fused: Wc0[k<512] = split(W_ih0 @ W_enc), gate-interleaved fp16
    gemm1_fused_kernel<<<dim3(DD / 128, GG / 64), 256, G1_SMEM>>>(
        W_ih0, p_B1hi, p_B1lo, p_Wc0hi, p_Wc0lo);

    build_cell_wh_kernel<<<2048, 128>>>(W_hh0, p_Wc0hi, p_Wc0lo);
    build_cell_w_kernel<<<2048, 256>>>(W_ih1, W_hh1, p_Wc1hi, p_Wc1lo);

    // ---- recurrence: one persistent launch ----
    lstm_persistent_kernel<<<NCTA, 256, PERS_SMEM>>>(
        p_Wc0hi, p_Wc0lo, p_Wc1hi, p_Wc1lo,
        p_h0fA, p_h0fB, p_h1zf, p_H1f, p_H1hi, p_H1lo,
        p_bias0, p_bias0f, p_bias1);

    // GEMM2: OUT(2560,10000) = H1 @ W_enc^T + b_enc  [bf16x3]
    gemm_bf16x3_kernel<2, 8><<<dim3((VV + 127) / 128, (TT * BB) / 256), 512, 196608>>>(
        p_H1hi, p_H1lo, p_B2hi, p_B2lo, out, b_enc, TT * BB, VV, DD);
}

// round 8
// speedup vs baseline: 1.3929x; 1.3929x over previous
#include <cuda_runtime.h>
#include <cuda_bf16.h>
#include <cuda_fp16.h>
#include <math.h>
#include <stdint.h>

#define BB 128     // batch
#define DD 512     // hidden
#define GG 2048    // 4*D
#define VV 10000   // vocab
#define TT 20      // timesteps
#define NCTA 128   // persistent kernel CTAs

// ---------------- device scratch (no allocation allowed) ----------------
__device__ float g_Mtmp[GG * DD];    // (2048,512)  W_ih0 @ W_enc (fp32)
__device__ float g_bias0[GG];
__device__ float g_bias0f[GG];
__device__ float g_bias1[GG];
__device__ unsigned g_bar;
// bf16 operands for the two big GEMMs
__device__ __nv_bfloat16 g_A1hi[(size_t)GG * VV];  // W_ih0 (2048,10000)
__device__ __nv_bfloat16 g_A1lo[(size_t)GG * VV];
__device__ __nv_bfloat16 g_B1hi[(size_t)DD * VV];  // W_enc^T rows=512, K=10000
__device__ __nv_bfloat16 g_B1lo[(size_t)DD * VV];
__device__ __nv_bfloat16 g_B2hi[(size_t)VV * DD];  // W_enc rows=10000, K=512
__device__ __nv_bfloat16 g_B2lo[(size_t)VV * DD];
__device__ __nv_bfloat16 g_H1hi[TT * BB * DD];     // h1 history for GEMM2 (bf16 hi/lo)
__device__ __nv_bfloat16 g_H1lo[TT * BB * DD];
// fp16 recurrence state
__device__ __half g_H1f[TT * BB * DD];             // h1 history (fp16, cell input)
__device__ __half g_h0fA[BB * DD], g_h0fB[BB * DD];
__device__ __half g_h1zf[BB * DD];
// fused, gate-interleaved cell weights (fp16 hi/lo): rows n'=d*4+gate, K=1024=[x|h]
__device__ __half g_Wc0hi[(size_t)GG * 1024];
__device__ __half g_Wc0lo[(size_t)GG * 1024];
__device__ __half g_Wc1hi[(size_t)GG * 1024];
__device__ __half g_Wc1lo[(size_t)GG * 1024];

// =========================================================================
// helpers
// =========================================================================
__device__ __forceinline__ uint32_t smem_u32(const void* p) {
    uint32_t a;
    asm("{ .reg .u64 t; cvta.to.shared.u64 t, %1; cvt.u32.u64 %0, t; }" : "=r"(a) : "l"(p));
    return a;
}
#define SWZ128(o) ((o) ^ (((o) >> 3) & 0x70))

__device__ __forceinline__ void ldsm_x4(uint32_t* r, uint32_t addr) {
    asm volatile("ldmatrix.sync.aligned.m8n8.x4.shared.b16 {%0,%1,%2,%3}, [%4];"
                 : "=r"(r[0]), "=r"(r[1]), "=r"(r[2]), "=r"(r[3]) : "r"(addr));
}
__device__ __forceinline__ void mma16816(float* d, const uint32_t* a, const uint32_t* b) {
    asm volatile(
        "mma.sync.aligned.m16n8k16.row.col.f32.bf16.bf16.f32 "
        "{%0,%1,%2,%3}, {%4,%5,%6,%7}, {%8,%9}, {%0,%1,%2,%3};"
        : "+f"(d[0]), "+f"(d[1]), "+f"(d[2]), "+f"(d[3])
        : "r"(a[0]), "r"(a[1]), "r"(a[2]), "r"(a[3]), "r"(b[0]), "r"(b[1]));
}
__device__ __forceinline__ void mma16816h(float* d, const uint32_t* a, const uint32_t* b) {
    asm volatile(
        "mma.sync.aligned.m16n8k16.row.col.f32.f16.f16.f32 "
        "{%0,%1,%2,%3}, {%4,%5,%6,%7}, {%8,%9}, {%0,%1,%2,%3};"
        : "+f"(d[0]), "+f"(d[1]), "+f"(d[2]), "+f"(d[3])
        : "r"(a[0]), "r"(a[1]), "r"(a[2]), "r"(a[3]), "r"(b[0]), "r"(b[1]));
}
__device__ __forceinline__ void cp_async16(uint32_t daddr, const void* g, unsigned sz) {
    asm volatile("cp.async.cg.shared.global [%0], [%1], 16, %2;"
                 :: "r"(daddr), "l"(g), "r"(sz));
}
#define CP_COMMIT() asm volatile("cp.async.commit_group;" ::: "memory")
#define CP_WAIT(n)  asm volatile("cp.async.wait_group %0;" :: "n"(n) : "memory")

// =========================================================================
// prep kernels
// =========================================================================
__global__ void zero_state_kernel() {
    int i = blockIdx.x * blockDim.x + threadIdx.x;
    if (i == 0) g_bar = 0u;
    if (i < BB * DD) g_h1zf[i] = __float2half_rn(0.f);
}

__global__ void bias_prep_kernel(const float* __restrict__ b_ih0, const float* __restrict__ b_hh0,
                                 const float* __restrict__ b_ih1, const float* __restrict__ b_hh1) {
    int g = blockIdx.x * blockDim.x + threadIdx.x;
    if (g < GG) {
        g_bias0[g] = b_ih0[g] + b_hh0[g];
        g_bias1[g] = b_ih1[g] + b_hh1[g];
    }
}

__global__ void bfused_kernel(const float* __restrict__ W_ih0, const float* __restrict__ b_enc) {
    __shared__ float red[256];
    int g = blockIdx.x;
    float s = 0.f;
    for (int v = threadIdx.x; v < VV; v += 256)
        s += W_ih0[(size_t)g * VV + v] * b_enc[v];
    red[threadIdx.x] = s;
    __syncthreads();
    for (int o = 128; o > 0; o >>= 1) {
        if (threadIdx.x < o) red[threadIdx.x] += red[threadIdx.x + o];
        __syncthreads();
    }
    if (threadIdx.x == 0) g_bias0f[g] = g_bias0[g] + red[0];
}

// W_enc (10000,512) fp32 -> B1hi/B1lo (512,10000) bf16 (fused transpose + split)
__global__ void transpose_split_kernel(const float* __restrict__ src,
                                       __nv_bfloat16* __restrict__ hi,
                                       __nv_bfloat16* __restrict__ lo) {
    __shared__ float tile[32][33];
    int c0 = blockIdx.x * 32;      // over 512 (cols of src)
    int r0 = blockIdx.y * 32;      // over 10000 (rows of src)
    int c = c0 + threadIdx.x;
    for (int i = threadIdx.y; i < 32; i += 8) {
        int r = r0 + i;
        if (r < VV) tile[i][threadIdx.x] = src[(size_t)r * DD + c];
    }
    __syncthreads();
    int r = r0 + threadIdx.x;      // dst col
    if (r < VV) {
        for (int i = threadIdx.y; i < 32; i += 8) {
            float v = tile[threadIdx.x][i];
            __nv_bfloat16 h = __float2bfloat16_rn(v);
            hi[(size_t)(c0 + i) * VV + r] = h;
            lo[(size_t)(c0 + i) * VV + r] = __float2bfloat16_rn(v - __bfloat162float(h));
        }
    }
}

// fp32 -> (bf16 hi, bf16 lo).  n divisible by 4.
__global__ void split_bf16_kernel(const float* __restrict__ src,
                                  __nv_bfloat16* __restrict__ hi,
                                  __nv_bfloat16* __restrict__ lo, int n) {
    int i = (blockIdx.x * blockDim.x + threadIdx.x) * 4;
    if (i < n) {
        float4 v = *(const float4*)(src + i);
        float vv[4] = {v.x, v.y, v.z, v.w};
        __nv_bfloat16 h[4], l[4];
        #pragma unroll
        for (int j = 0; j < 4; j++) {
            h[j] = __float2bfloat16_rn(vv[j]);
            l[j] = __float2bfloat16_rn(vv[j] - __bfloat162float(h[j]));
        }
        *(uint2*)(hi + i) = *(uint2*)h;
        *(uint2*)(lo + i) = *(uint2*)l;
    }
}

__global__ void f32_to_f16_kernel(const float* __restrict__ src, __half* __restrict__ dst, int n) {
    int i = (blockIdx.x * blockDim.x + threadIdx.x) * 4;
    if (i < n) {
        float4 v = *(const float4*)(src + i);
        __half h[4] = {__float2half_rn(v.x), __float2half_rn(v.y),
                       __float2half_rn(v.z), __float2half_rn(v.w)};
        *(uint2*)(dst + i) = *(uint2*)h;
    }
}

// fused cell weights (fp16 hi/lo): out (2048,1024): n'=d*4+gate, src n=gate*512+d,
// k<512 from srcX else srcH. grid=2048, block=256.
__global__ void build_cell_w_kernel(const float* __restrict__ srcX, const float* __restrict__ srcH,
                                    __half* __restrict__ whi, __half* __restrict__ wlo) {
    int idx = blockIdx.x * 256 + threadIdx.x;
    int e = idx * 4;
    int np = e >> 10, k4 = e & 1023;
    int d = np >> 2, gate = np & 3;
    int n = gate * 512 + d;
    const float* s = (k4 < 512) ? (srcX + (size_t)n * 512 + k4)
                                : (srcH + (size_t)n * 512 + (k4 - 512));
    float4 v = *(const float4*)s;
    float vv[4] = {v.x, v.y, v.z, v.w};
    __half h[4], l[4];
    #pragma unroll
    for (int j = 0; j < 4; j++) {
        h[j] = __float2half_rn(vv[j]);
        l[j] = __float2half_rn(vv[j] - __half2float(h[j]));
    }
    *(uint2*)(whi + (size_t)np * 1024 + k4) = *(uint2*)h;
    *(uint2*)(wlo + (size_t)np * 1024 + k4) = *(uint2*)l;
}

// =========================================================================
// mma.sync bf16x3 GEMM:  C(M,N) = A(M,K) * B(N,K)^T (+bias)
// BM = MW*MT*16, BN = 128, BK = 64. MW*2 warps.
// =========================================================================
template<int MT, int MW>
__global__ __launch_bounds__(MW * 64) void gemm_bf16x3_kernel(
    const __nv_bfloat16* __restrict__ Ahi, const __nv_bfloat16* __restrict__ Alo,
    const __nv_bfloat16* __restrict__ Bhi, const __nv_bfloat16* __restrict__ Blo,
    float* __restrict__ C, const float* __restrict__ bias,
    int Mtot, int Ntot, int Ktot)
{
    constexpr int BM = MW * MT * 16;
    constexpr int NTH = MW * 64;
    constexpr int ABYTES = BM * 128;
    constexpr int BUFBYTES = 2 * ABYTES + 32768;
    extern __shared__ char smem[];
    const uint32_t sb = smem_u32(smem);
    const int tid = threadIdx.x, wid = tid >> 5, lane = tid & 31;
    const int wm = wid % MW, wn = wid / MW;
    const int m0 = blockIdx.y * BM, n0 = blockIdx.x * 128;
    const int NT = (Ktot + 63) / 64;

    float acc[MT][8][4];
    #pragma unroll
    for (int mt = 0; mt < MT; mt++)
        #pragma unroll
        for (int nt = 0; nt < 8; nt++)
            #pragma unroll
            for (int j = 0; j < 4; j++) acc[mt][nt][j] = 0.f;

    auto load_chunk = [&](int kt, int buf) {
        const int kc = kt * 64;
        const uint32_t bufbase = sb + buf * BUFBYTES;
        #pragma unroll
        for (int w = 0; w < 2; w++) {
            const __nv_bfloat16* src = w ? Alo : Ahi;
            uint32_t tdst = bufbase + w * ABYTES;
            for (int i = tid; i < BM * 8; i += NTH) {
                int r = i >> 3, c16 = i & 7;
                int gr = m0 + r, gk = kc + c16 * 8;
                bool inb = (gr < Mtot) && (gk < Ktot);
                cp_async16(tdst + SWZ128(r * 128 + c16 * 16),
                           src + (inb ? ((size_t)gr * Ktot + gk) : 0), inb ? 16u : 0u);
            }
        }
        #pragma unroll
        for (int w = 0; w < 2; w++) {
            const __nv_bfloat16* src = w ? Blo : Bhi;
            uint32_t tdst = bufbase + 2 * ABYTES + w * 16384;
            for (int i = tid; i < 1024; i += NTH) {
                int r = i >> 3, c16 = i & 7;
                int gr = n0 + r, gk = kc + c16 * 8;
                bool inb = (gr < Ntot) && (gk < Ktot);
                cp_async16(tdst + SWZ128(r * 128 + c16 * 16),
                           src + (inb ? ((size_t)gr * Ktot + gk) : 0), inb ? 16u : 0u);
            }
        }
        CP_COMMIT();
    };

    load_chunk(0, 0);
    const int g8 = lane >> 3, rg = lane & 7;

    for (int kt = 0; kt < NT; kt++) {
        const int buf = kt & 1;
        if (kt + 1 < NT) { load_chunk(kt + 1, buf ^ 1); CP_WAIT(1); }
        else             { CP_WAIT(0); }
        __syncthreads();

        const uint32_t bAh = sb + buf * BUFBYTES;
        const uint32_t bAl = bAh + ABYTES;
        const uint32_t bBh = bAh + 2 * ABYTES;
        const uint32_t bBl = bBh + 16384;

        #pragma unroll
        for (int kk = 0; kk < 4; kk++) {
            const int kb = kk * 32;
            uint32_t ah[MT][4], al[MT][4], bh[8][2], bl[8][2];
            #pragma unroll
            for (int mt = 0; mt < MT; mt++) {
                int row = wm * (16 * MT) + mt * 16 + (g8 & 1) * 8 + rg;
                uint32_t off = SWZ128(row * 128 + kb + (g8 >> 1) * 16);
                ldsm_x4(ah[mt], bAh + off);
                ldsm_x4(al[mt], bAl + off);
            }
            #pragma unroll
            for (int p = 0; p < 4; p++) {
                int rowb = wn * 64 + p * 16 + (g8 >> 1) * 8 + rg;
                uint32_t off = SWZ128(rowb * 128 + kb + (g8 & 1) * 16);
                uint32_t t[4];
                ldsm_x4(t, bBh + off);
                bh[2 * p][0] = t[0]; bh[2 * p][1] = t[1];
                bh[2 * p + 1][0] = t[2]; bh[2 * p + 1][1] = t[3];
                ldsm_x4(t, bBl + off);
                bl[2 * p][0] = t[0]; bl[2 * p][1] = t[1];
                bl[2 * p + 1][0] = t[2]; bl[2 * p + 1][1] = t[3];
            }
            #pragma unroll
            for (int mt = 0; mt < MT; mt++)
                #pragma unroll
                for (int nt = 0; nt < 8; nt++) {
                    mma16816(acc[mt][nt], ah[mt], bh[nt]);
                    mma16816(acc[mt][nt], ah[mt], bl[nt]);
                    mma16816(acc[mt][nt], al[mt], bh[nt]);
                }
        }
        __syncthreads();
    }

    #pragma unroll
    for (int mt = 0; mt < MT; mt++) {
        int row = m0 + wm * (16 * MT) + mt * 16 + (lane >> 2);
        #pragma unroll
        for (int nt = 0; nt < 8; nt++) {
            int col = n0 + wn * 64 + nt * 8 + (lane & 3) * 2;
            if (col < Ntot) {
                float b0 = 0.f, b1 = 0.f;
                if (bias) { b0 = bias[col]; b1 = bias[col + 1]; }
                float2 v0 = make_float2(acc[mt][nt][0] + b0, acc[mt][nt][1] + b1);
                float2 v1 = make_float2(acc[mt][nt][2] + b0, acc[mt][nt][3] + b1);
                *(float2*)&C[(size_t)row * Ntot + col] = v0;
                *(float2*)&C[(size_t)(row + 8) * Ntot + col] = v1;
            }
        }
    }
}

// =========================================================================
// persistent LSTM recurrence, fp16 2-term (A fp16 single, W fp16 hi/lo).
// 128 CTAs x 256 threads; CTA b owns gate rows n0 = b*16 (d in [b*4,b*4+4)).
// smem: W0 64K | W1 64K | A dbuf 32K | gates 8K = 168K
// =========================================================================
#define PSM_W0 0
#define PSM_W1 65536
#define PSM_A  131072
#define PSM_G  163840
#define PERS_SMEM 172032

__global__ __launch_bounds__(256) void lstm_persistent_kernel(
    const __half* __restrict__ Wc0hi, const __half* __restrict__ Wc0lo,
    const __half* __restrict__ Wc1hi, const __half* __restrict__ Wc1lo,
    __half* __restrict__ h0fA, __half* __restrict__ h0fB,
    const __half* __restrict__ h1zf, __half* __restrict__ H1f,
    __nv_bfloat16* __restrict__ H1hi, __nv_bfloat16* __restrict__ H1lo,
    const float* __restrict__ bias0, const float* __restrict__ bias0f,
    const float* __restrict__ bias1)
{
    extern __shared__ char smem[];
    const uint32_t sb = smem_u32(smem);
    float* gates = (float*)(smem + PSM_G);
    const int tid = threadIdx.x, wid = tid >> 5, lane = tid & 31;
    const int n0 = blockIdx.x * 16;
    const int g8 = lane >> 3, rg = lane & 7;

    // persistent weight slices (both layers, hi+lo)
    {
        const __half* srcs[4] = {Wc0hi, Wc0lo, Wc1hi, Wc1lo};
        const uint32_t dsts[4] = {PSM_W0, PSM_W0 + 32768, PSM_W1, PSM_W1 + 32768};
        #pragma unroll
        for (int w = 0; w < 4; w++) {
            const __half* src = srcs[w];
            #pragma unroll
            for (int it = 0; it < 8; it++) {
                int i = it * 256 + tid;
                int ch = i >> 7, r = (i >> 3) & 15, c16 = i & 7;
                cp_async16(sb + dsts[w] + ch * 2048 + SWZ128(r * 128 + c16 * 16),
                           src + (size_t)(n0 + r) * 1024 + ch * 64 + c16 * 8, 16);
            }
        }
        CP_COMMIT();
    }

    float rb0[2][4], rb0f[2][4], rb1[2][4];
    #pragma unroll
    for (int it = 0; it < 2; it++) {
        int idx = it * 256 + tid;
        int dd = idx & 3;
        int d = blockIdx.x * 4 + dd;
        #pragma unroll
        for (int gte = 0; gte < 4; gte++) {
            rb0[it][gte]  = bias0[gte * 512 + d];
            rb0f[it][gte] = bias0f[gte * 512 + d];
            rb1[it][gte]  = bias1[gte * 512 + d];
        }
    }

    float c0r[2] = {0.f, 0.f}, c1r[2] = {0.f, 0.f};
    unsigned epoch = 0;
    int cur = 0;

    for (int t = 0; t < TT; t++) {
        #pragma unroll
        for (int layer = 0; layer < 2; layer++) {
            const __half *xf, *hf;
            int kstart;
            if (layer == 0) {
                kstart = (t == 0) ? 8 : 0;
                xf = (t == 0) ? (const __half*)0 : H1f + (size_t)(t - 1) * BB * DD;
                hf = cur ? h0fB : h0fA;
            } else {
                kstart = 0;
                xf = cur ? h0fA : h0fB;     // newly written h0
                hf = (t == 0) ? h1zf : H1f + (size_t)(t - 1) * BB * DD;
            }
            const uint32_t wbase = sb + (layer ? PSM_W1 : PSM_W0);

            auto load_chunk = [&](int ch, int buf) {
                const __half* src = (ch < 8) ? xf : hf;
                int koff = (ch & 7) * 64;
                const uint32_t base = sb + PSM_A + buf * 16384;
                #pragma unroll
                for (int it = 0; it < 4; it++) {
                    int i = it * 256 + tid;
                    int r = i >> 3, c16 = i & 7;
                    cp_async16(base + SWZ128(r * 128 + c16 * 16),
                               src + (size_t)r * 512 + koff + c16 * 8, 16);
                }
                CP_COMMIT();
            };

            float acc[2][4];
            #pragma unroll
            for (int b = 0; b < 2; b++)
                #pragma unroll
                for (int j = 0; j < 4; j++) acc[b][j] = 0.f;

            load_chunk(kstart, 0);
            for (int ch = kstart; ch < 16; ch++) {
                const int buf = (ch - kstart) & 1;
                if (ch + 1 < 16) { load_chunk(ch + 1, buf ^ 1); CP_WAIT(1); }
                else             { CP_WAIT(0); }
                __syncthreads();

                const uint32_t bA = sb + PSM_A + buf * 16384;
                const uint32_t bW = wbase + ch * 2048;
                const uint32_t bWl = bW + 32768;

                #pragma unroll
                for (int kk = 0; kk < 4; kk++) {
                    const int kb = kk * 32;
                    uint32_t a4[4], tw[4], twl[4];
                    int row = wid * 16 + (g8 & 1) * 8 + rg;
                    ldsm_x4(a4, bA + SWZ128(row * 128 + kb + (g8 >> 1) * 16));
                    int rowb = (g8 >> 1) * 8 + rg;
                    uint32_t offB = SWZ128(rowb * 128 + kb + (g8 & 1) * 16);
                    ldsm_x4(tw, bW + offB);
                    ldsm_x4(twl, bWl + offB);
                    uint32_t bh0[2] = {tw[0], tw[1]},  bh1[2] = {tw[2], tw[3]};
                    uint32_t bl0[2] = {twl[0], twl[1]}, bl1[2] = {twl[2], twl[3]};
                    mma16816h(acc[0], a4, bh0);
                    mma16816h(acc[0], a4, bl0);
                    mma16816h(acc[1], a4, bh1);
                    mma16816h(acc[1], a4, bl1);
                }
                __syncthreads();
            }

            {
                int r0 = wid * 16 + (lane >> 2);
                int cb = (lane & 3) * 2;
                #pragma unroll
                for (int b = 0; b < 2; b++) {
                    gates[r0 * 16 + b * 8 + cb]           = acc[b][0];
                    gates[r0 * 16 + b * 8 + cb + 1]       = acc[b][1];
                    gates[(r0 + 8) * 16 + b * 8 + cb]     = acc[b][2];
                    gates[(r0 + 8) * 16 + b * 8 + cb + 1] = acc[b][3];
                }
            }
            __syncthreads();

            __half* of0 = cur ? h0fA : h0fB;
            __half* of1 = H1f + (size_t)t * BB * DD;
            __nv_bfloat16* ohh = H1hi + (size_t)t * BB * DD;
            __nv_bfloat16* ohl = H1lo + (size_t)t * BB * DD;
            #pragma unroll
            for (int it = 0; it < 2; it++) {
                int idx = it * 256 + tid;
                int row = idx >> 2, dd = idx & 3;
                int d = blockIdx.x * 4 + dd;
                const float* rb = (layer == 0) ? ((t == 0) ? rb0[it] : rb0f[it]) : rb1[it];
                float gi = gates[row * 16 + dd * 4 + 0] + rb[0];
                float gf = gates[row * 16 + dd * 4 + 1] + rb[1];
                float gg = gates[row * 16 + dd * 4 + 2] + rb[2];
                float go = gates[row * 16 + dd * 4 + 3] + rb[3];
                float i_ = 1.f / (1.f + expf(-gi));
                float f_ = 1.f / (1.f + expf(-gf));
                float g_ = tanhf(gg);
                float o_ = 1.f / (1.f + expf(-go));
                float* cr = (layer == 0) ? &c0r[it] : &c1r[it];
                float cn = f_ * (*cr) + i_ * g_;
                *cr = cn;
                float hv = o_ * tanhf(cn);
                if (layer == 0) {
                    of0[row * 512 + d] = __float2half_rn(hv);
                } else {
                    of1[row * 512 + d] = __float2half_rn(hv);
                    __nv_bfloat16 hb = __float2bfloat16_rn(hv);
                    ohh[row * 512 + d] = hb;
                    ohl[row * 512 + d] = __float2bfloat16_rn(hv - __bfloat162float(hb));
                }
            }

            __threadfence();
            __syncthreads();
            epoch++;
            if (tid == 0) {
                atomicAdd(&g_bar, 1u);
                unsigned target = epoch * NCTA;
                volatile unsigned* p = &g_bar;
                while (*p < target) { }
                __threadfence();
            }
            __syncthreads();
        }
        cur ^= 1;
    }
}

// =========================================================================
// host
// =========================================================================
extern "C" void kernel_launch(void* const* d_in, const int* in_sizes, int n_in,
                              void* d_out, int out_size) {
    const float* input_ = (const float*)d_in[0];
    const float* W_ih0  = (const float*)d_in[1];
    const float* W_hh0  = (const float*)d_in[2];
    const float* b_ih0  = (const float*)d_in[3];
    const float* b_hh0  = (const float*)d_in[4];
    const float* W_ih1  = (const float*)d_in[5];
    const float* W_hh1  = (const float*)d_in[6];
    const float* b_ih1  = (const float*)d_in[7];
    const float* b_hh1  = (const float*)d_in[8];
    const float* W_enc  = (const float*)d_in[9];
    const float* b_enc  = (const float*)d_in[10];
    float* out = (float*)d_out;

    float *p_Mtmp, *p_bias0, *p_bias0f, *p_bias1;
    __nv_bfloat16 *p_A1hi, *p_A1lo, *p_B1hi, *p_B1lo, *p_B2hi, *p_B2lo, *p_H1hi, *p_H1lo;
    __half *p_H1f, *p_h0fA, *p_h0fB, *p_h1zf;
    __half *p_Wc0hi, *p_Wc0lo, *p_Wc1hi, *p_Wc1lo;
    cudaGetSymbolAddress((void**)&p_Mtmp,   g_Mtmp);
    cudaGetSymbolAddress((void**)&p_bias0,  g_bias0);
    cudaGetSymbolAddress((void**)&p_bias0f, g_bias0f);
    cudaGetSymbolAddress((void**)&p_bias1,  g_bias1);
    cudaGetSymbolAddress((void**)&p_A1hi,   g_A1hi);
    cudaGetSymbolAddress((void**)&p_A1lo,   g_A1lo);
    cudaGetSymbolAddress((void**)&p_B1hi,   g_B1hi);
    cudaGetSymbolAddress((void**)&p_B1lo,   g_B1lo);
    cudaGetSymbolAddress((void**)&p_B2hi,   g_B2hi);
    cudaGetSymbolAddress((void**)&p_B2lo,   g_B2lo);
    cudaGetSymbolAddress((void**)&p_H1hi,   g_H1hi);
    cudaGetSymbolAddress((void**)&p_H1lo,   g_H1lo);
    cudaGetSymbolAddress((void**)&p_H1f,    g_H1f);
    cudaGetSymbolAddress((void**)&p_h0fA,   g_h0fA);
    cudaGetSymbolAddress((void**)&p_h0fB,   g_h0fB);
    cudaGetSymbolAddress((void**)&p_h1zf,   g_h1zf);
    cudaGetSymbolAddress((void**)&p_Wc0hi,  g_Wc0hi);
    cudaGetSymbolAddress((void**)&p_Wc0lo,  g_Wc0lo);
    cudaGetSymbolAddress((void**)&p_Wc1hi,  g_Wc1hi);
    cudaGetSymbolAddress((void**)&p_Wc1lo,  g_Wc1lo);

    cudaFuncSetAttribute((const void*)gemm_bf16x3_kernel<1, 4>,
                         cudaFuncAttributeMaxDynamicSharedMemorySize, 98304);
    cudaFuncSetAttribute((const void*)gemm_bf16x3_kernel<2, 8>,
                         cudaFuncAttributeMaxDynamicSharedMemorySize, 196608);
    cudaFuncSetAttribute((const void*)lstm_persistent_kernel,
                         cudaFuncAttributeMaxDynamicSharedMemorySize, PERS_SMEM);

    // ---- prep ----
    zero_state_kernel<<<(BB * DD + 255) / 256, 256>>>();
    bias_prep_kernel<<<(GG + 255) / 256, 256>>>(b_ih0, b_hh0, b_ih1, b_hh1);
    bfused_kernel<<<GG, 256>>>(W_ih0, b_enc);

    dim3 tb(32, 8);
    transpose_split_kernel<<<dim3(DD / 32, (VV + 31) / 32), tb>>>(W_enc, p_B1hi, p_B1lo);
    {
        int n1 = GG * VV;
        split_bf16_kernel<<<(n1 / 4 + 255) / 256, 256>>>(W_ih0, p_A1hi, p_A1lo, n1);
        split_bf16_kernel<<<(VV * DD / 4 + 255) / 256, 256>>>(W_enc, p_B2hi, p_B2lo, VV * DD);
        f32_to_f16_kernel<<<(BB * DD / 4 + 255) / 256, 256>>>(input_, p_h0fA, BB * DD);
    }

    // GEMM1: Mtmp(2048,512) = W_ih0 @ W_enc^T   [bf16x3, BM=64, grid 128]
    gemm_bf16x3_kernel<1, 4><<<dim3(DD / 128, GG / 64), 256, 98304>>>(
        p_A1hi, p_A1lo, p_B1hi, p_B1lo, p_Mtmp, nullptr, GG, DD, VV);

    // fused, gate-interleaved fp16 cell weights
    build_cell_w_kernel<<<2048, 256>>>(p_Mtmp, W_hh0, p_Wc0hi, p_Wc0lo);
    build_cell_w_kernel<<<2048, 256>>>(W_ih1, W_hh1, p_Wc1hi, p_Wc1lo);

    // ---- recurrence: one persistent launch ----
    lstm_persistent_kernel<<<NCTA, 256, PERS_SMEM>>>(
        p_Wc0hi, p_Wc0lo, p_Wc1hi, p_Wc1lo,
        p_h0fA, p_h0fB, p_h1zf, p_H1f, p_H1hi, p_H1lo,
        p_bias0, p_bias0f, p_bias1);

    // GEMM2: OUT(2560,10000) = H1 @ W_enc^T + b_enc  [bf16x3]
    gemm_bf16x3_kernel<2, 8><<<dim3((VV + 127) / 128, (TT * BB) / 256), 512, 196608>>>(
        p_H1hi, p_H1lo, p_B2hi, p_B2lo, out, b_enc, TT * BB, VV, DD);
}

// round 9
// speedup vs baseline: 1.5724x; 1.1289x over previous
#include <cuda_runtime.h>
#include <cuda_bf16.h>
#include <cuda_fp16.h>
#include <math.h>
#include <stdint.h>

#define BB 128     // batch
#define DD 512     // hidden
#define GG 2048    // 4*D
#define VV 10000   // vocab
#define TT 20      // timesteps
#define NCTA 128   // persistent kernel CTAs

// ---------------- device scratch (no allocation allowed) ----------------
__device__ float g_Mtmp[GG * DD];    // (2048,512)  W_ih0 @ W_enc (fp32)
__device__ float g_bias0[GG];
__device__ float g_bias0f[GG];
__device__ float g_bias1[GG];
__device__ unsigned g_bar;
// bf16 operands for GEMM1
__device__ __nv_bfloat16 g_A1hi[(size_t)GG * VV];  // W_ih0 (2048,10000)
__device__ __nv_bfloat16 g_A1lo[(size_t)GG * VV];
__device__ __nv_bfloat16 g_B1hi[(size_t)DD * VV];  // W_enc^T rows=512, K=10000
__device__ __nv_bfloat16 g_B1lo[(size_t)DD * VV];
// fp16 operands for GEMM2
__device__ __half g_B2fhi[(size_t)VV * DD];        // W_enc rows=10000, K=512 (fp16 hi/lo)
__device__ __half g_B2flo[(size_t)VV * DD];
// fp16 recurrence state
__device__ __half g_H1f[TT * BB * DD];             // h1 history (cell input + GEMM2 A)
__device__ __half g_h0fA[BB * DD], g_h0fB[BB * DD];
__device__ __half g_h1zf[BB * DD];
// fused, gate-interleaved cell weights (fp16 hi/lo): rows n'=d*4+gate, K=1024=[x|h]
__device__ __half g_Wc0hi[(size_t)GG * 1024];
__device__ __half g_Wc0lo[(size_t)GG * 1024];
__device__ __half g_Wc1hi[(size_t)GG * 1024];
__device__ __half g_Wc1lo[(size_t)GG * 1024];

// =========================================================================
// helpers
// =========================================================================
__device__ __forceinline__ uint32_t smem_u32(const void* p) {
    uint32_t a;
    asm("{ .reg .u64 t; cvta.to.shared.u64 t, %1; cvt.u32.u64 %0, t; }" : "=r"(a) : "l"(p));
    return a;
}
#define SWZ128(o) ((o) ^ (((o) >> 3) & 0x70))

__device__ __forceinline__ void ldsm_x4(uint32_t* r, uint32_t addr) {
    asm volatile("ldmatrix.sync.aligned.m8n8.x4.shared.b16 {%0,%1,%2,%3}, [%4];"
                 : "=r"(r[0]), "=r"(r[1]), "=r"(r[2]), "=r"(r[3]) : "r"(addr));
}
__device__ __forceinline__ void mma16816(float* d, const uint32_t* a, const uint32_t* b) {
    asm volatile(
        "mma.sync.aligned.m16n8k16.row.col.f32.bf16.bf16.f32 "
        "{%0,%1,%2,%3}, {%4,%5,%6,%7}, {%8,%9}, {%0,%1,%2,%3};"
        : "+f"(d[0]), "+f"(d[1]), "+f"(d[2]), "+f"(d[3])
        : "r"(a[0]), "r"(a[1]), "r"(a[2]), "r"(a[3]), "r"(b[0]), "r"(b[1]));
}
__device__ __forceinline__ void mma16816h(float* d, const uint32_t* a, const uint32_t* b) {
    asm volatile(
        "mma.sync.aligned.m16n8k16.row.col.f32.f16.f16.f32 "
        "{%0,%1,%2,%3}, {%4,%5,%6,%7}, {%8,%9}, {%0,%1,%2,%3};"
        : "+f"(d[0]), "+f"(d[1]), "+f"(d[2]), "+f"(d[3])
        : "r"(a[0]), "r"(a[1]), "r"(a[2]), "r"(a[3]), "r"(b[0]), "r"(b[1]));
}
__device__ __forceinline__ void cp_async16(uint32_t daddr, const void* g, unsigned sz) {
    asm volatile("cp.async.cg.shared.global [%0], [%1], 16, %2;"
                 :: "r"(daddr), "l"(g), "r"(sz));
}
#define CP_COMMIT() asm volatile("cp.async.commit_group;" ::: "memory")
#define CP_WAIT(n)  asm volatile("cp.async.wait_group %0;" :: "n"(n) : "memory")

// =========================================================================
// prep kernels
// =========================================================================
// merged: barrier reset + bias sums + h1 zero + h0 fp16 convert
__global__ void prep_misc_kernel(const float* __restrict__ input_,
                                 const float* __restrict__ b_ih0, const float* __restrict__ b_hh0,
                                 const float* __restrict__ b_ih1, const float* __restrict__ b_hh1) {
    int i = blockIdx.x * blockDim.x + threadIdx.x;
    if (i == 0) g_bar = 0u;
    if (i < GG) {
        g_bias0[i] = b_ih0[i] + b_hh0[i];
        g_bias1[i] = b_ih1[i] + b_hh1[i];
    }
    if (i < BB * DD) g_h1zf[i] = __float2half_rn(0.f);
    if (i < BB * DD / 4) {
        float4 v = *(const float4*)(input_ + i * 4);
        __half h[4] = {__float2half_rn(v.x), __float2half_rn(v.y),
                       __float2half_rn(v.z), __float2half_rn(v.w)};
        *(uint2*)(g_h0fA + i * 4) = *(uint2*)h;
    }
}

__global__ void bfused_kernel(const float* __restrict__ W_ih0, const float* __restrict__ b_enc) {
    __shared__ float red[256];
    int g = blockIdx.x;
    float s = 0.f;
    for (int v = threadIdx.x; v < VV; v += 256)
        s += W_ih0[(size_t)g * VV + v] * b_enc[v];
    red[threadIdx.x] = s;
    __syncthreads();
    for (int o = 128; o > 0; o >>= 1) {
        if (threadIdx.x < o) red[threadIdx.x] += red[threadIdx.x + o];
        __syncthreads();
    }
    if (threadIdx.x == 0) g_bias0f[g] = g_bias0[g] + red[0];
}

// W_enc (10000,512) fp32 -> B1hi/B1lo (512,10000) bf16 (fused transpose + split)
__global__ void transpose_split_kernel(const float* __restrict__ src,
                                       __nv_bfloat16* __restrict__ hi,
                                       __nv_bfloat16* __restrict__ lo) {
    __shared__ float tile[32][33];
    int c0 = blockIdx.x * 32;
    int r0 = blockIdx.y * 32;
    int c = c0 + threadIdx.x;
    for (int i = threadIdx.y; i < 32; i += 8) {
        int r = r0 + i;
        if (r < VV) tile[i][threadIdx.x] = src[(size_t)r * DD + c];
    }
    __syncthreads();
    int r = r0 + threadIdx.x;
    if (r < VV) {
        for (int i = threadIdx.y; i < 32; i += 8) {
            float v = tile[threadIdx.x][i];
            __nv_bfloat16 h = __float2bfloat16_rn(v);
            hi[(size_t)(c0 + i) * VV + r] = h;
            lo[(size_t)(c0 + i) * VV + r] = __float2bfloat16_rn(v - __bfloat162float(h));
        }
    }
}

// fp32 -> (bf16 hi, bf16 lo).
__global__ void split_bf16_kernel(const float* __restrict__ src,
                                  __nv_bfloat16* __restrict__ hi,
                                  __nv_bfloat16* __restrict__ lo, int n) {
    int i = (blockIdx.x * blockDim.x + threadIdx.x) * 4;
    if (i < n) {
        float4 v = *(const float4*)(src + i);
        float vv[4] = {v.x, v.y, v.z, v.w};
        __nv_bfloat16 h[4], l[4];
        #pragma unroll
        for (int j = 0; j < 4; j++) {
            h[j] = __float2bfloat16_rn(vv[j]);
            l[j] = __float2bfloat16_rn(vv[j] - __bfloat162float(h[j]));
        }
        *(uint2*)(hi + i) = *(uint2*)h;
        *(uint2*)(lo + i) = *(uint2*)l;
    }
}

// fp32 -> (fp16 hi, fp16 lo).
__global__ void split_f16_kernel(const float* __restrict__ src,
                                 __half* __restrict__ hi, __half* __restrict__ lo, int n) {
    int i = (blockIdx.x * blockDim.x + threadIdx.x) * 4;
    if (i < n) {
        float4 v = *(const float4*)(src + i);
        float vv[4] = {v.x, v.y, v.z, v.w};
        __half h[4], l[4];
        #pragma unroll
        for (int j = 0; j < 4; j++) {
            h[j] = __float2half_rn(vv[j]);
            l[j] = __float2half_rn(vv[j] - __half2float(h[j]));
        }
        *(uint2*)(hi + i) = *(uint2*)h;
        *(uint2*)(lo + i) = *(uint2*)l;
    }
}

// fused cell weights (fp16 hi/lo): out (2048,1024): n'=d*4+gate, src n=gate*512+d,
// k<512 from srcX else srcH. grid=2048, block=256.
__global__ void build_cell_w_kernel(const float* __restrict__ srcX, const float* __restrict__ srcH,
                                    __half* __restrict__ whi, __half* __restrict__ wlo) {
    int idx = blockIdx.x * 256 + threadIdx.x;
    int e = idx * 4;
    int np = e >> 10, k4 = e & 1023;
    int d = np >> 2, gate = np & 3;
    int n = gate * 512 + d;
    const float* s = (k4 < 512) ? (srcX + (size_t)n * 512 + k4)
                                : (srcH + (size_t)n * 512 + (k4 - 512));
    float4 v = *(const float4*)s;
    float vv[4] = {v.x, v.y, v.z, v.w};
    __half h[4], l[4];
    #pragma unroll
    for (int j = 0; j < 4; j++) {
        h[j] = __float2half_rn(vv[j]);
        l[j] = __float2half_rn(vv[j] - __half2float(h[j]));
    }
    *(uint2*)(whi + (size_t)np * 1024 + k4) = *(uint2*)h;
    *(uint2*)(wlo + (size_t)np * 1024 + k4) = *(uint2*)l;
}

// =========================================================================
// GEMM1 (bf16x3):  C(M,N) = A(M,K) * B(N,K)^T.  BM=64, BN=128, BK=64.
// =========================================================================
template<int MT, int MW>
__global__ __launch_bounds__(MW * 64) void gemm_bf16x3_kernel(
    const __nv_bfloat16* __restrict__ Ahi, const __nv_bfloat16* __restrict__ Alo,
    const __nv_bfloat16* __restrict__ Bhi, const __nv_bfloat16* __restrict__ Blo,
    float* __restrict__ C, const float* __restrict__ bias,
    int Mtot, int Ntot, int Ktot)
{
    constexpr int BM = MW * MT * 16;
    constexpr int NTH = MW * 64;
    constexpr int ABYTES = BM * 128;
    constexpr int BUFBYTES = 2 * ABYTES + 32768;
    extern __shared__ char smem[];
    const uint32_t sb = smem_u32(smem);
    const int tid = threadIdx.x, wid = tid >> 5, lane = tid & 31;
    const int wm = wid % MW, wn = wid / MW;
    const int m0 = blockIdx.y * BM, n0 = blockIdx.x * 128;
    const int NT = (Ktot + 63) / 64;

    float acc[MT][8][4];
    #pragma unroll
    for (int mt = 0; mt < MT; mt++)
        #pragma unroll
        for (int nt = 0; nt < 8; nt++)
            #pragma unroll
            for (int j = 0; j < 4; j++) acc[mt][nt][j] = 0.f;

    auto load_chunk = [&](int kt, int buf) {
        const int kc = kt * 64;
        const uint32_t bufbase = sb + buf * BUFBYTES;
        #pragma unroll
        for (int w = 0; w < 2; w++) {
            const __nv_bfloat16* src = w ? Alo : Ahi;
            uint32_t tdst = bufbase + w * ABYTES;
            for (int i = tid; i < BM * 8; i += NTH) {
                int r = i >> 3, c16 = i & 7;
                int gr = m0 + r, gk = kc + c16 * 8;
                bool inb = (gr < Mtot) && (gk < Ktot);
                cp_async16(tdst + SWZ128(r * 128 + c16 * 16),
                           src + (inb ? ((size_t)gr * Ktot + gk) : 0), inb ? 16u : 0u);
            }
        }
        #pragma unroll
        for (int w = 0; w < 2; w++) {
            const __nv_bfloat16* src = w ? Blo : Bhi;
            uint32_t tdst = bufbase + 2 * ABYTES + w * 16384;
            for (int i = tid; i < 1024; i += NTH) {
                int r = i >> 3, c16 = i & 7;
                int gr = n0 + r, gk = kc + c16 * 8;
                bool inb = (gr < Ntot) && (gk < Ktot);
                cp_async16(tdst + SWZ128(r * 128 + c16 * 16),
                           src + (inb ? ((size_t)gr * Ktot + gk) : 0), inb ? 16u : 0u);
            }
        }
        CP_COMMIT();
    };

    load_chunk(0, 0);
    const int g8 = lane >> 3, rg = lane & 7;

    for (int kt = 0; kt < NT; kt++) {
        const int buf = kt & 1;
        if (kt + 1 < NT) { load_chunk(kt + 1, buf ^ 1); CP_WAIT(1); }
        else             { CP_WAIT(0); }
        __syncthreads();

        const uint32_t bAh = sb + buf * BUFBYTES;
        const uint32_t bAl = bAh + ABYTES;
        const uint32_t bBh = bAh + 2 * ABYTES;
        const uint32_t bBl = bBh + 16384;

        #pragma unroll
        for (int kk = 0; kk < 4; kk++) {
            const int kb = kk * 32;
            uint32_t ah[MT][4], al[MT][4], bh[8][2], bl[8][2];
            #pragma unroll
            for (int mt = 0; mt < MT; mt++) {
                int row = wm * (16 * MT) + mt * 16 + (g8 & 1) * 8 + rg;
                uint32_t off = SWZ128(row * 128 + kb + (g8 >> 1) * 16);
                ldsm_x4(ah[mt], bAh + off);
                ldsm_x4(al[mt], bAl + off);
            }
            #pragma unroll
            for (int p = 0; p < 4; p++) {
                int rowb = wn * 64 + p * 16 + (g8 >> 1) * 8 + rg;
                uint32_t off = SWZ128(rowb * 128 + kb + (g8 & 1) * 16);
                uint32_t t[4];
                ldsm_x4(t, bBh + off);
                bh[2 * p][0] = t[0]; bh[2 * p][1] = t[1];
                bh[2 * p + 1][0] = t[2]; bh[2 * p + 1][1] = t[3];
                ldsm_x4(t, bBl + off);
                bl[2 * p][0] = t[0]; bl[2 * p][1] = t[1];
                bl[2 * p + 1][0] = t[2]; bl[2 * p + 1][1] = t[3];
            }
            #pragma unroll
            for (int mt = 0; mt < MT; mt++)
                #pragma unroll
                for (int nt = 0; nt < 8; nt++) {
                    mma16816(acc[mt][nt], ah[mt], bh[nt]);
                    mma16816(acc[mt][nt], ah[mt], bl[nt]);
                    mma16816(acc[mt][nt], al[mt], bh[nt]);
                }
        }
        __syncthreads();
    }

    #pragma unroll
    for (int mt = 0; mt < MT; mt++) {
        int row = m0 + wm * (16 * MT) + mt * 16 + (lane >> 2);
        #pragma unroll
        for (int nt = 0; nt < 8; nt++) {
            int col = n0 + wn * 64 + nt * 8 + (lane & 3) * 2;
            if (col < Ntot) {
                float b0 = 0.f, b1 = 0.f;
                if (bias) { b0 = bias[col]; b1 = bias[col + 1]; }
                float2 v0 = make_float2(acc[mt][nt][0] + b0, acc[mt][nt][1] + b1);
                float2 v1 = make_float2(acc[mt][nt][2] + b0, acc[mt][nt][3] + b1);
                *(float2*)&C[(size_t)row * Ntot + col] = v0;
                *(float2*)&C[(size_t)(row + 8) * Ntot + col] = v1;
            }
        }
    }
}

// =========================================================================
// GEMM2 (fp16 2-term): OUT(M,N) = A(M,K)fp16 * (Bhi+Blo)(N,K)^T + bias.
// BM=256, BN=128, BK=64; 16 warps (8m x 2n), 512 threads.
// smem/buf: A 32KB | Bhi 16KB | Blo 16KB = 64KB; x2 = 128KB.
// =========================================================================
#define G2_BUF 65536
#define G2_SMEM (2 * G2_BUF)

__global__ __launch_bounds__(512) void gemm_f16x2_kernel(
    const __half* __restrict__ A,
    const __half* __restrict__ Bhi, const __half* __restrict__ Blo,
    float* __restrict__ C, const float* __restrict__ bias,
    int Mtot, int Ntot, int Ktot)
{
    constexpr int BM = 256;
    extern __shared__ char smem[];
    const uint32_t sb = smem_u32(smem);
    const int tid = threadIdx.x, wid = tid >> 5, lane = tid & 31;
    const int wm = wid & 7, wn = wid >> 3;
    const int m0 = blockIdx.y * BM, n0 = blockIdx.x * 128;
    const int NT = (Ktot + 63) / 64;   // 8

    float acc[2][8][4];
    #pragma unroll
    for (int mt = 0; mt < 2; mt++)
        #pragma unroll
        for (int nt = 0; nt < 8; nt++)
            #pragma unroll
            for (int j = 0; j < 4; j++) acc[mt][nt][j] = 0.f;

    auto load_chunk = [&](int kt, int buf) {
        const int kc = kt * 64;
        const uint32_t bufbase = sb + buf * G2_BUF;
        // A: 256 rows x 8 x 16B = 2048 ops / 512 thr = 4 iters
        #pragma unroll
        for (int it = 0; it < 4; it++) {
            int i = it * 512 + tid;
            int r = i >> 3, c16 = i & 7;
            cp_async16(bufbase + SWZ128(r * 128 + c16 * 16),
                       A + (size_t)(m0 + r) * Ktot + kc + c16 * 8, 16);
        }
        // B hi/lo: 128 rows x 8 each
        #pragma unroll
        for (int w = 0; w < 2; w++) {
            const __half* src = w ? Blo : Bhi;
            uint32_t tdst = bufbase + 32768 + w * 16384;
            #pragma unroll
            for (int it = 0; it < 2; it++) {
                int i = it * 512 + tid;
                int r = i >> 3, c16 = i & 7;
                int gr = n0 + r;
                bool inb = gr < Ntot;
                cp_async16(tdst + SWZ128(r * 128 + c16 * 16),
                           src + (inb ? ((size_t)gr * Ktot + kc + c16 * 8) : 0), inb ? 16u : 0u);
            }
        }
        CP_COMMIT();
    };

    load_chunk(0, 0);
    const int g8 = lane >> 3, rg = lane & 7;

    for (int kt = 0; kt < NT; kt++) {
        const int buf = kt & 1;
        if (kt + 1 < NT) { load_chunk(kt + 1, buf ^ 1); CP_WAIT(1); }
        else             { CP_WAIT(0); }
        __syncthreads();

        const uint32_t bA = sb + buf * G2_BUF;
        const uint32_t bBh = bA + 32768;
        const uint32_t bBl = bA + 49152;

        #pragma unroll
        for (int kk = 0; kk < 4; kk++) {
            const int kb = kk * 32;
            uint32_t a4[2][4], bh[8][2], bl[8][2];
            #pragma unroll
            for (int mt = 0; mt < 2; mt++) {
                int row = wm * 32 + mt * 16 + (g8 & 1) * 8 + rg;
                ldsm_x4(a4[mt], bA + SWZ128(row * 128 + kb + (g8 >> 1) * 16));
            }
            #pragma unroll
            for (int p = 0; p < 4; p++) {
                int rowb = wn * 64 + p * 16 + (g8 >> 1) * 8 + rg;
                uint32_t off = SWZ128(rowb * 128 + kb + (g8 & 1) * 16);
                uint32_t t[4];
                ldsm_x4(t, bBh + off);
                bh[2 * p][0] = t[0]; bh[2 * p][1] = t[1];
                bh[2 * p + 1][0] = t[2]; bh[2 * p + 1][1] = t[3];
                ldsm_x4(t, bBl + off);
                bl[2 * p][0] = t[0]; bl[2 * p][1] = t[1];
                bl[2 * p + 1][0] = t[2]; bl[2 * p + 1][1] = t[3];
            }
            #pragma unroll
            for (int mt = 0; mt < 2; mt++)
                #pragma unroll
                for (int nt = 0; nt < 8; nt++) {
                    mma16816h(acc[mt][nt], a4[mt], bh[nt]);
                    mma16816h(acc[mt][nt], a4[mt], bl[nt]);
                }
        }
        __syncthreads();
    }

    #pragma unroll
    for (int mt = 0; mt < 2; mt++) {
        int row = m0 + wm * 32 + mt * 16 + (lane >> 2);
        #pragma unroll
        for (int nt = 0; nt < 8; nt++) {
            int col = n0 + wn * 64 + nt * 8 + (lane & 3) * 2;
            if (col < Ntot) {
                float b0 = bias[col], b1 = bias[col + 1];
                float2 v0 = make_float2(acc[mt][nt][0] + b0, acc[mt][nt][1] + b1);
                float2 v1 = make_float2(acc[mt][nt][2] + b0, acc[mt][nt][3] + b1);
                *(float2*)&C[(size_t)row * Ntot + col] = v0;
                *(float2*)&C[(size_t)(row + 8) * Ntot + col] = v1;
            }
        }
    }
}

// =========================================================================
// persistent LSTM recurrence, fp16 2-term (A fp16 single, W fp16 hi/lo).
// 128 CTAs x 256 threads; CTA b owns gate rows n0 = b*16 (d in [b*4,b*4+4)).
// smem: W0 64K | W1 64K | A dbuf 32K | gates 8K = 168K
// =========================================================================
#define PSM_W0 0
#define PSM_W1 65536
#define PSM_A  131072
#define PSM_G  163840
#define PERS_SMEM 172032

__global__ __launch_bounds__(256) void lstm_persistent_kernel(
    const __half* __restrict__ Wc0hi, const __half* __restrict__ Wc0lo,
    const __half* __restrict__ Wc1hi, const __half* __restrict__ Wc1lo,
    __half* __restrict__ h0fA, __half* __restrict__ h0fB,
    const __half* __restrict__ h1zf, __half* __restrict__ H1f,
    const float* __restrict__ bias0, const float* __restrict__ bias0f,
    const float* __restrict__ bias1)
{
    extern __shared__ char smem[];
    const uint32_t sb = smem_u32(smem);
    float* gates = (float*)(smem + PSM_G);
    const int tid = threadIdx.x, wid = tid >> 5, lane = tid & 31;
    const int n0 = blockIdx.x * 16;
    const int g8 = lane >> 3, rg = lane & 7;

    // persistent weight slices (both layers, hi+lo)
    {
        const __half* srcs[4] = {Wc0hi, Wc0lo, Wc1hi, Wc1lo};
        const uint32_t dsts[4] = {PSM_W0, PSM_W0 + 32768, PSM_W1, PSM_W1 + 32768};
        #pragma unroll
        for (int w = 0; w < 4; w++) {
            const __half* src = srcs[w];
            #pragma unroll
            for (int it = 0; it < 8; it++) {
                int i = it * 256 + tid;
                int ch = i >> 7, r = (i >> 3) & 15, c16 = i & 7;
                cp_async16(sb + dsts[w] + ch * 2048 + SWZ128(r * 128 + c16 * 16),
                           src + (size_t)(n0 + r) * 1024 + ch * 64 + c16 * 8, 16);
            }
        }
        CP_COMMIT();
    }

    float rb0[2][4], rb0f[2][4], rb1[2][4];
    #pragma unroll
    for (int it = 0; it < 2; it++) {
        int idx = it * 256 + tid;
        int dd = idx & 3;
        int d = blockIdx.x * 4 + dd;
        #pragma unroll
        for (int gte = 0; gte < 4; gte++) {
            rb0[it][gte]  = bias0[gte * 512 + d];
            rb0f[it][gte] = bias0f[gte * 512 + d];
            rb1[it][gte]  = bias1[gte * 512 + d];
        }
    }

    float c0r[2] = {0.f, 0.f}, c1r[2] = {0.f, 0.f};
    unsigned epoch = 0;
    int cur = 0;

    for (int t = 0; t < TT; t++) {
        #pragma unroll
        for (int layer = 0; layer < 2; layer++) {
            const __half *xf, *hf;
            int kstart;
            if (layer == 0) {
                kstart = (t == 0) ? 8 : 0;
                xf = (t == 0) ? (const __half*)0 : H1f + (size_t)(t - 1) * BB * DD;
                hf = cur ? h0fB : h0fA;
            } else {
                kstart = 0;
                xf = cur ? h0fA : h0fB;     // newly written h0
                hf = (t == 0) ? h1zf : H1f + (size_t)(t - 1) * BB * DD;
            }
            const uint32_t wbase = sb + (layer ? PSM_W1 : PSM_W0);

            auto load_chunk = [&](int ch, int buf) {
                const __half* src = (ch < 8) ? xf : hf;
                int koff = (ch & 7) * 64;
                const uint32_t base = sb + PSM_A + buf * 16384;
                #pragma unroll
                for (int it = 0; it < 4; it++) {
                    int i = it * 256 + tid;
                    int r = i >> 3, c16 = i & 7;
                    cp_async16(base + SWZ128(r * 128 + c16 * 16),
                               src + (size_t)r * 512 + koff + c16 * 8, 16);
                }
                CP_COMMIT();
            };

            float acc[2][4];
            #pragma unroll
            for (int b = 0; b < 2; b++)
                #pragma unroll
                for (int j = 0; j < 4; j++) acc[b][j] = 0.f;

            load_chunk(kstart, 0);
            for (int ch = kstart; ch < 16; ch++) {
                const int buf = (ch - kstart) & 1;
                if (ch + 1 < 16) { load_chunk(ch + 1, buf ^ 1); CP_WAIT(1); }
                else             { CP_WAIT(0); }
                __syncthreads();

                const uint32_t bA = sb + PSM_A + buf * 16384;
                const uint32_t bW = wbase + ch * 2048;
                const uint32_t bWl = bW + 32768;

                #pragma unroll
                for (int kk = 0; kk < 4; kk++) {
                    const int kb = kk * 32;
                    uint32_t a4[4], tw[4], twl[4];
                    int row = wid * 16 + (g8 & 1) * 8 + rg;
                    ldsm_x4(a4, bA + SWZ128(row * 128 + kb + (g8 >> 1) * 16));
                    int rowb = (g8 >> 1) * 8 + rg;
                    uint32_t offB = SWZ128(rowb * 128 + kb + (g8 & 1) * 16);
                    ldsm_x4(tw, bW + offB);
                    ldsm_x4(twl, bWl + offB);
                    uint32_t bh0[2] = {tw[0], tw[1]},  bh1[2] = {tw[2], tw[3]};
                    uint32_t bl0[2] = {twl[0], twl[1]}, bl1[2] = {twl[2], twl[3]};
                    mma16816h(acc[0], a4, bh0);
                    mma16816h(acc[0], a4, bl0);
                    mma16816h(acc[1], a4, bh1);
                    mma16816h(acc[1], a4, bl1);
                }
                __syncthreads();
            }

            {
                int r0 = wid * 16 + (lane >> 2);
                int cb = (lane & 3) * 2;
                #pragma unroll
                for (int b = 0; b < 2; b++) {
                    gates[r0 * 16 + b * 8 + cb]           = acc[b][0];
                    gates[r0 * 16 + b * 8 + cb + 1]       = acc[b][1];
                    gates[(r0 + 8) * 16 + b * 8 + cb]     = acc[b][2];
                    gates[(r0 + 8) * 16 + b * 8 + cb + 1] = acc[b][3];
                }
            }
            __syncthreads();

            __half* of = (layer == 0) ? (cur ? h0fA : h0fB) : (H1f + (size_t)t * BB * DD);
            #pragma unroll
            for (int it = 0; it < 2; it++) {
                int idx = it * 256 + tid;
                int row = idx >> 2, dd = idx & 3;
                int d = blockIdx.x * 4 + dd;
                const float* rb = (layer == 0) ? ((t == 0) ? rb0[it] : rb0f[it]) : rb1[it];
                float gi = gates[row * 16 + dd * 4 + 0] + rb[0];
                float gf = gates[row * 16 + dd * 4 + 1] + rb[1];
                float gg = gates[row * 16 + dd * 4 + 2] + rb[2];
                float go = gates[row * 16 + dd * 4 + 3] + rb[3];
                float i_ = 1.f / (1.f + expf(-gi));
                float f_ = 1.f / (1.f + expf(-gf));
                float g_ = tanhf(gg);
                float o_ = 1.f / (1.f + expf(-go));
                float* cr = (layer == 0) ? &c0r[it] : &c1r[it];
                float cn = f_ * (*cr) + i_ * g_;
                *cr = cn;
                of[row * 512 + d] = __float2half_rn(o_ * tanhf(cn));
            }

            __threadfence();
            __syncthreads();
            epoch++;
            if (tid == 0) {
                atomicAdd(&g_bar, 1u);
                unsigned target = epoch * NCTA;
                volatile unsigned* p = &g_bar;
                while (*p < target) { }
                __threadfence();
            }
            __syncthreads();
        }
        cur ^= 1;
    }
}

// =========================================================================
// host
// =========================================================================
extern "C" void kernel_launch(void* const* d_in, const int* in_sizes, int n_in,
                              void* d_out, int out_size) {
    const float* input_ = (const float*)d_in[0];
    const float* W_ih0  = (const float*)d_in[1];
    const float* W_hh0  = (const float*)d_in[2];
    const float* b_ih0  = (const float*)d_in[3];
    const float* b_hh0  = (const float*)d_in[4];
    const float* W_ih1  = (const float*)d_in[5];
    const float* W_hh1  = (const float*)d_in[6];
    const float* b_ih1  = (const float*)d_in[7];
    const float* b_hh1  = (const float*)d_in[8];
    const float* W_enc  = (const float*)d_in[9];
    const float* b_enc  = (const float*)d_in[10];
    float* out = (float*)d_out;

    float *p_Mtmp, *p_bias0, *p_bias0f, *p_bias1;
    __nv_bfloat16 *p_A1hi, *p_A1lo, *p_B1hi, *p_B1lo;
    __half *p_B2fhi, *p_B2flo, *p_H1f, *p_h0fA, *p_h0fB, *p_h1zf;
    __half *p_Wc0hi, *p_Wc0lo, *p_Wc1hi, *p_Wc1lo;
    cudaGetSymbolAddress((void**)&p_Mtmp,   g_Mtmp);
    cudaGetSymbolAddress((void**)&p_bias0,  g_bias0);
    cudaGetSymbolAddress((void**)&p_bias0f, g_bias0f);
    cudaGetSymbolAddress((void**)&p_bias1,  g_bias1);
    cudaGetSymbolAddress((void**)&p_A1hi,   g_A1hi);
    cudaGetSymbolAddress((void**)&p_A1lo,   g_A1lo);
    cudaGetSymbolAddress((void**)&p_B1hi,   g_B1hi);
    cudaGetSymbolAddress((void**)&p_B1lo,   g_B1lo);
    cudaGetSymbolAddress((void**)&p_B2fhi,  g_B2fhi);
    cudaGetSymbolAddress((void**)&p_B2flo,  g_B2flo);
    cudaGetSymbolAddress((void**)&p_H1f,    g_H1f);
    cudaGetSymbolAddress((void**)&p_h0fA,   g_h0fA);
    cudaGetSymbolAddress((void**)&p_h0fB,   g_h0fB);
    cudaGetSymbolAddress((void**)&p_h1zf,   g_h1zf);
    cudaGetSymbolAddress((void**)&p_Wc0hi,  g_Wc0hi);
    cudaGetSymbolAddress((void**)&p_Wc0lo,  g_Wc0lo);
    cudaGetSymbolAddress((void**)&p_Wc1hi,  g_Wc1hi);
    cudaGetSymbolAddress((void**)&p_Wc1lo,  g_Wc1lo);

    cudaFuncSetAttribute((const void*)gemm_bf16x3_kernel<1, 4>,
                         cudaFuncAttributeMaxDynamicSharedMemorySize, 98304);
    cudaFuncSetAttribute((const void*)gemm_f16x2_kernel,
                         cudaFuncAttributeMaxDynamicSharedMemorySize, G2_SMEM);
    cudaFuncSetAttribute((const void*)lstm_persistent_kernel,
                         cudaFuncAttributeMaxDynamicSharedMemorySize, PERS_SMEM);

    // ---- prep ----
    prep_misc_kernel<<<(BB * DD + 255) / 256, 256>>>(input_, b_ih0, b_hh0, b_ih1, b_hh1);
    bfused_kernel<<<GG, 256>>>(W_ih0, b_enc);

    dim3 tb(32, 8);
    transpose_split_kernel<<<dim3(DD / 32, (VV + 31) / 32), tb>>>(W_enc, p_B1hi, p_B1lo);
    {
        int n1 = GG * VV;
        split_bf16_kernel<<<(n1 / 4 + 255) / 256, 256>>>(W_ih0, p_A1hi, p_A1lo, n1);
        split_f16_kernel<<<(VV * DD / 4 + 255) / 256, 256>>>(W_enc, p_B2fhi, p_B2flo, VV * DD);
    }

    // GEMM1: Mtmp(2048,512) = W_ih0 @ W_enc^T   [bf16x3, BM=64, grid 128]
    gemm_bf16x3_kernel<1, 4><<<dim3(DD / 128, GG / 64), 256, 98304>>>(
        p_A1hi, p_A1lo, p_B1hi, p_B1lo, p_Mtmp, nullptr, GG, DD, VV);

    // fused, gate-interleaved fp16 cell weights
    build_cell_w_kernel<<<2048, 256>>>(p_Mtmp, W_hh0, p_Wc0hi, p_Wc0lo);
    build_cell_w_kernel<<<2048, 256>>>(W_ih1, W_hh1, p_Wc1hi, p_Wc1lo);

    // ---- recurrence: one persistent launch ----
    lstm_persistent_kernel<<<NCTA, 256, PERS_SMEM>>>(
        p_Wc0hi, p_Wc0lo, p_Wc1hi, p_Wc1lo,
        p_h0fA, p_h0fB, p_h1zf, p_H1f,
        p_bias0, p_bias0f, p_bias1);

    // GEMM2: OUT(2560,10000) = H1f @ (B2hi+B2lo)^T + b_enc  [fp16 2-term]
    gemm_f16x2_kernel<<<dim3((VV + 127) / 128, (TT * BB) / 256), 512, G2_SMEM>>>(
        p_H1f, p_B2fhi, p_B2flo, out, b_enc, TT * BB, VV, DD);
}

// round 10
// speedup vs baseline: 1.8509x; 1.1772x over previous
#include <cuda_runtime.h>
#include <cuda_bf16.h>
#include <cuda_fp16.h>
#include <math.h>
#include <stdint.h>

#define BB 128     // batch
#define DD 512     // hidden
#define GG 2048    // 4*D
#define VV 10000   // vocab
#define TT 20      // timesteps
#define NCTA 128   // persistent kernel CTAs

// ---------------- device scratch (no allocation allowed) ----------------
__device__ float g_Mtmp[GG * DD];    // (2048,512)  W_ih0 @ W_enc (fp32, split-K red target)
__device__ float g_bias0[GG];
__device__ float g_bias0f[GG];
__device__ float g_bias1[GG];
__device__ unsigned g_bar;
// fp16 operands for GEMM1
__device__ __half g_A1f[(size_t)GG * VV];          // W_ih0 (2048,10000) fp16 single
__device__ __half g_B1fhi[(size_t)DD * VV];        // W_enc^T rows=512, K=10000 (fp16 hi/lo)
__device__ __half g_B1flo[(size_t)DD * VV];
// fp16 operands for GEMM2
__device__ __half g_B2fhi[(size_t)VV * DD];        // W_enc rows=10000, K=512 (fp16 hi/lo)
__device__ __half g_B2flo[(size_t)VV * DD];
// fp16 recurrence state
__device__ __half g_H1f[TT * BB * DD];             // h1 history (cell input + GEMM2 A)
__device__ __half g_h0fA[BB * DD], g_h0fB[BB * DD];
__device__ __half g_h1zf[BB * DD];
// fused, gate-interleaved cell weights (fp16 hi/lo): rows n'=d*4+gate, K=1024=[x|h]
__device__ __half g_Wc0hi[(size_t)GG * 1024];
__device__ __half g_Wc0lo[(size_t)GG * 1024];
__device__ __half g_Wc1hi[(size_t)GG * 1024];
__device__ __half g_Wc1lo[(size_t)GG * 1024];

// =========================================================================
// helpers
// =========================================================================
__device__ __forceinline__ uint32_t smem_u32(const void* p) {
    uint32_t a;
    asm("{ .reg .u64 t; cvta.to.shared.u64 t, %1; cvt.u32.u64 %0, t; }" : "=r"(a) : "l"(p));
    return a;
}
#define SWZ128(o) ((o) ^ (((o) >> 3) & 0x70))

__device__ __forceinline__ void ldsm_x4(uint32_t* r, uint32_t addr) {
    asm volatile("ldmatrix.sync.aligned.m8n8.x4.shared.b16 {%0,%1,%2,%3}, [%4];"
                 : "=r"(r[0]), "=r"(r[1]), "=r"(r[2]), "=r"(r[3]) : "r"(addr));
}
__device__ __forceinline__ void mma16816h(float* d, const uint32_t* a, const uint32_t* b) {
    asm volatile(
        "mma.sync.aligned.m16n8k16.row.col.f32.f16.f16.f32 "
        "{%0,%1,%2,%3}, {%4,%5,%6,%7}, {%8,%9}, {%0,%1,%2,%3};"
        : "+f"(d[0]), "+f"(d[1]), "+f"(d[2]), "+f"(d[3])
        : "r"(a[0]), "r"(a[1]), "r"(a[2]), "r"(a[3]), "r"(b[0]), "r"(b[1]));
}
__device__ __forceinline__ void cp_async16(uint32_t daddr, const void* g, unsigned sz) {
    asm volatile("cp.async.cg.shared.global [%0], [%1], 16, %2;"
                 :: "r"(daddr), "l"(g), "r"(sz));
}
__device__ __forceinline__ void red_addf(float* p, float v) {
    asm volatile("red.global.add.f32 [%0], %1;" :: "l"(p), "f"(v) : "memory");
}
#define CP_COMMIT() asm volatile("cp.async.commit_group;" ::: "memory")
#define CP_WAIT(n)  asm volatile("cp.async.wait_group %0;" :: "n"(n) : "memory")

// =========================================================================
// prep kernels
// =========================================================================
__global__ void prep_misc_kernel(const float* __restrict__ input_,
                                 const float* __restrict__ b_ih0, const float* __restrict__ b_hh0,
                                 const float* __restrict__ b_ih1, const float* __restrict__ b_hh1) {
    int i = blockIdx.x * blockDim.x + threadIdx.x;
    if (i == 0) g_bar = 0u;
    if (i < GG) {
        g_bias0[i] = b_ih0[i] + b_hh0[i];
        g_bias1[i] = b_ih1[i] + b_hh1[i];
    }
    if (i < BB * DD) g_h1zf[i] = __float2half_rn(0.f);
    if (i < BB * DD / 4) {
        float4 v = *(const float4*)(input_ + i * 4);
        __half h[4] = {__float2half_rn(v.x), __float2half_rn(v.y),
                       __float2half_rn(v.z), __float2half_rn(v.w)};
        *(uint2*)(g_h0fA + i * 4) = *(uint2*)h;
    }
}

__global__ void bfused_kernel(const float* __restrict__ W_ih0, const float* __restrict__ b_enc) {
    __shared__ float red[256];
    int g = blockIdx.x;
    float s = 0.f;
    for (int v = threadIdx.x; v < VV; v += 256)
        s += W_ih0[(size_t)g * VV + v] * b_enc[v];
    red[threadIdx.x] = s;
    __syncthreads();
    for (int o = 128; o > 0; o >>= 1) {
        if (threadIdx.x < o) red[threadIdx.x] += red[threadIdx.x + o];
        __syncthreads();
    }
    if (threadIdx.x == 0) g_bias0f[g] = g_bias0[g] + red[0];
}

// W_enc (10000,512) fp32 -> B1fhi/B1flo (512,10000) fp16 (fused transpose + split)
__global__ void transpose_split_f16_kernel(const float* __restrict__ src,
                                           __half* __restrict__ hi,
                                           __half* __restrict__ lo) {
    __shared__ float tile[32][33];
    int c0 = blockIdx.x * 32;
    int r0 = blockIdx.y * 32;
    int c = c0 + threadIdx.x;
    for (int i = threadIdx.y; i < 32; i += 8) {
        int r = r0 + i;
        if (r < VV) tile[i][threadIdx.x] = src[(size_t)r * DD + c];
    }
    __syncthreads();
    int r = r0 + threadIdx.x;
    if (r < VV) {
        for (int i = threadIdx.y; i < 32; i += 8) {
            float v = tile[threadIdx.x][i];
            __half h = __float2half_rn(v);
            hi[(size_t)(c0 + i) * VV + r] = h;
            lo[(size_t)(c0 + i) * VV + r] = __float2half_rn(v - __half2float(h));
        }
    }
}

// fp32 -> fp16 single
__global__ void f32_to_f16_kernel(const float* __restrict__ src, __half* __restrict__ dst, int n) {
    int i = (blockIdx.x * blockDim.x + threadIdx.x) * 4;
    if (i < n) {
        float4 v = *(const float4*)(src + i);
        __half h[4] = {__float2half_rn(v.x), __float2half_rn(v.y),
                       __float2half_rn(v.z), __float2half_rn(v.w)};
        *(uint2*)(dst + i) = *(uint2*)h;
    }
}

// fp32 -> (fp16 hi, fp16 lo)
__global__ void split_f16_kernel(const float* __restrict__ src,
                                 __half* __restrict__ hi, __half* __restrict__ lo, int n) {
    int i = (blockIdx.x * blockDim.x + threadIdx.x) * 4;
    if (i < n) {
        float4 v = *(const float4*)(src + i);
        float vv[4] = {v.x, v.y, v.z, v.w};
        __half h[4], l[4];
        #pragma unroll
        for (int j = 0; j < 4; j++) {
            h[j] = __float2half_rn(vv[j]);
            l[j] = __float2half_rn(vv[j] - __half2float(h[j]));
        }
        *(uint2*)(hi + i) = *(uint2*)h;
        *(uint2*)(lo + i) = *(uint2*)l;
    }
}

// fused cell weights (fp16 hi/lo): out (2048,1024): n'=d*4+gate, src n=gate*512+d,
// k<512 from srcX else srcH. grid=2048, block=256.
__global__ void build_cell_w_kernel(const float* __restrict__ srcX, const float* __restrict__ srcH,
                                    __half* __restrict__ whi, __half* __restrict__ wlo) {
    int idx = blockIdx.x * 256 + threadIdx.x;
    int e = idx * 4;
    int np = e >> 10, k4 = e & 1023;
    int d = np >> 2, gate = np & 3;
    int n = gate * 512 + d;
    const float* s = (k4 < 512) ? (srcX + (size_t)n * 512 + k4)
                                : (srcH + (size_t)n * 512 + (k4 - 512));
    float4 v = *(const float4*)s;
    float vv[4] = {v.x, v.y, v.z, v.w};
    __half h[4], l[4];
    #pragma unroll
    for (int j = 0; j < 4; j++) {
        h[j] = __float2half_rn(vv[j]);
        l[j] = __float2half_rn(vv[j] - __half2float(h[j]));
    }
    *(uint2*)(whi + (size_t)np * 1024 + k4) = *(uint2*)h;
    *(uint2*)(wlo + (size_t)np * 1024 + k4) = *(uint2*)l;
}

// =========================================================================
// GEMM1 (fp16 2-term, split-K=2): Mtmp(2048,512) += A(2048,10000)f16 @ (Bhi+Blo)(512,10000)^T
// BM=128 (MT=2, MW=4, 256 thr), BN=128, BK=64. grid = (4, 16, 2).
// Epilogue: red.global.add.f32 into zeroed Mtmp (2 adds/elt = order-commutative).
// smem/buf: A 16K | Bhi 16K | Blo 16K = 48K; x2 = 96K.
// =========================================================================
#define G1_BUF 49152
#define G1_SMEM (2 * G1_BUF)
#define KSPLIT (VV / 2)   // 5000

__global__ __launch_bounds__(256) void gemm1_f16x2_kernel(
    const __half* __restrict__ A,
    const __half* __restrict__ Bhi, const __half* __restrict__ Blo,
    float* __restrict__ C)
{
    extern __shared__ char smem[];
    const uint32_t sb = smem_u32(smem);
    const int tid = threadIdx.x, wid = tid >> 5, lane = tid & 31;
    const int wm = wid & 3, wn = wid >> 2;
    const int m0 = blockIdx.y * 128, n0 = blockIdx.x * 128;
    const int kb0 = blockIdx.z * KSPLIT;
    const int kend = kb0 + KSPLIT;
    const int NT = (KSPLIT + 63) / 64;   // 79

    float acc[2][8][4];
    #pragma unroll
    for (int mt = 0; mt < 2; mt++)
        #pragma unroll
        for (int nt = 0; nt < 8; nt++)
            #pragma unroll
            for (int j = 0; j < 4; j++) acc[mt][nt][j] = 0.f;

    auto load_chunk = [&](int kt, int buf) {
        const int kc = kb0 + kt * 64;
        const uint32_t bufbase = sb + buf * G1_BUF;
        // A: 128 rows x 8 x 16B = 1024 ops / 256 thr
        #pragma unroll
        for (int it = 0; it < 4; it++) {
            int i = it * 256 + tid;
            int r = i >> 3, c16 = i & 7;
            int gk = kc + c16 * 8;
            bool inb = gk < kend;
            cp_async16(bufbase + SWZ128(r * 128 + c16 * 16),
                       A + (inb ? ((size_t)(m0 + r) * VV + gk) : 0), inb ? 16u : 0u);
        }
        // Bhi/Blo: 128 rows x 8 each
        #pragma unroll
        for (int w = 0; w < 2; w++) {
            const __half* src = w ? Blo : Bhi;
            uint32_t tdst = bufbase + 16384 + w * 16384;
            #pragma unroll
            for (int it = 0; it < 4; it++) {
                int i = it * 256 + tid;
                int r = i >> 3, c16 = i & 7;
                int gk = kc + c16 * 8;
                bool inb = gk < kend;
                cp_async16(tdst + SWZ128(r * 128 + c16 * 16),
                           src + (inb ? ((size_t)(n0 + r) * VV + gk) : 0), inb ? 16u : 0u);
            }
        }
        CP_COMMIT();
    };

    load_chunk(0, 0);
    const int g8 = lane >> 3, rg = lane & 7;

    for (int kt = 0; kt < NT; kt++) {
        const int buf = kt & 1;
        if (kt + 1 < NT) { load_chunk(kt + 1, buf ^ 1); CP_WAIT(1); }
        else             { CP_WAIT(0); }
        __syncthreads();

        const uint32_t bA = sb + buf * G1_BUF;
        const uint32_t bBh = bA + 16384;
        const uint32_t bBl = bA + 32768;

        #pragma unroll
        for (int kk = 0; kk < 4; kk++) {
            const int kb = kk * 32;
            uint32_t a4[2][4], bh[8][2], bl[8][2];
            #pragma unroll
            for (int mt = 0; mt < 2; mt++) {
                int row = wm * 32 + mt * 16 + (g8 & 1) * 8 + rg;
                ldsm_x4(a4[mt], bA + SWZ128(row * 128 + kb + (g8 >> 1) * 16));
            }
            #pragma unroll
            for (int p = 0; p < 4; p++) {
                int rowb = wn * 64 + p * 16 + (g8 >> 1) * 8 + rg;
                uint32_t off = SWZ128(rowb * 128 + kb + (g8 & 1) * 16);
                uint32_t t[4];
                ldsm_x4(t, bBh + off);
                bh[2 * p][0] = t[0]; bh[2 * p][1] = t[1];
                bh[2 * p + 1][0] = t[2]; bh[2 * p + 1][1] = t[3];
                ldsm_x4(t, bBl + off);
                bl[2 * p][0] = t[0]; bl[2 * p][1] = t[1];
                bl[2 * p + 1][0] = t[2]; bl[2 * p + 1][1] = t[3];
            }
            #pragma unroll
            for (int mt = 0; mt < 2; mt++)
                #pragma unroll
                for (int nt = 0; nt < 8; nt++) {
                    mma16816h(acc[mt][nt], a4[mt], bh[nt]);
                    mma16816h(acc[mt][nt], a4[mt], bl[nt]);
                }
        }
        __syncthreads();
    }

    // reduction epilogue
    #pragma unroll
    for (int mt = 0; mt < 2; mt++) {
        int row = m0 + wm * 32 + mt * 16 + (lane >> 2);
        #pragma unroll
        for (int nt = 0; nt < 8; nt++) {
            int col = n0 + wn * 64 + nt * 8 + (lane & 3) * 2;
            float* p0 = &C[(size_t)row * DD + col];
            float* p1 = &C[(size_t)(row + 8) * DD + col];
            red_addf(p0, acc[mt][nt][0]);
            red_addf(p0 + 1, acc[mt][nt][1]);
            red_addf(p1, acc[mt][nt][2]);
            red_addf(p1 + 1, acc[mt][nt][3]);
        }
    }
}

// =========================================================================
// GEMM2 (fp16 2-term): OUT(M,N) = A(M,K)fp16 * (Bhi+Blo)(N,K)^T + bias.
// BM=256, BN=128, BK=64; 16 warps (8m x 2n), 512 threads. (unchanged from R9)
// =========================================================================
#define G2_BUF 65536
#define G2_SMEM (2 * G2_BUF)

__global__ __launch_bounds__(512) void gemm_f16x2_kernel(
    const __half* __restrict__ A,
    const __half* __restrict__ Bhi, const __half* __restrict__ Blo,
    float* __restrict__ C, const float* __restrict__ bias,
    int Mtot, int Ntot, int Ktot)
{
    constexpr int BM = 256;
    extern __shared__ char smem[];
    const uint32_t sb = smem_u32(smem);
    const int tid = threadIdx.x, wid = tid >> 5, lane = tid & 31;
    const int wm = wid & 7, wn = wid >> 3;
    const int m0 = blockIdx.y * BM, n0 = blockIdx.x * 128;
    const int NT = (Ktot + 63) / 64;

    float acc[2][8][4];
    #pragma unroll
    for (int mt = 0; mt < 2; mt++)
        #pragma unroll
        for (int nt = 0; nt < 8; nt++)
            #pragma unroll
            for (int j = 0; j < 4; j++) acc[mt][nt][j] = 0.f;

    auto load_chunk = [&](int kt, int buf) {
        const int kc = kt * 64;
        const uint32_t bufbase = sb + buf * G2_BUF;
        #pragma unroll
        for (int it = 0; it < 4; it++) {
            int i = it * 512 + tid;
            int r = i >> 3, c16 = i & 7;
            cp_async16(bufbase + SWZ128(r * 128 + c16 * 16),
                       A + (size_t)(m0 + r) * Ktot + kc + c16 * 8, 16);
        }
        #pragma unroll
        for (int w = 0; w < 2; w++) {
            const __half* src = w ? Blo : Bhi;
            uint32_t tdst = bufbase + 32768 + w * 16384;
            #pragma unroll
            for (int it = 0; it < 2; it++) {
                int i = it * 512 + tid;
                int r = i >> 3, c16 = i & 7;
                int gr = n0 + r;
                bool inb = gr < Ntot;
                cp_async16(tdst + SWZ128(r * 128 + c16 * 16),
                           src + (inb ? ((size_t)gr * Ktot + kc + c16 * 8) : 0), inb ? 16u : 0u);
            }
        }
        CP_COMMIT();
    };

    load_chunk(0, 0);
    const int g8 = lane >> 3, rg = lane & 7;

    for (int kt = 0; kt < NT; kt++) {
        const int buf = kt & 1;
        if (kt + 1 < NT) { load_chunk(kt + 1, buf ^ 1); CP_WAIT(1); }
        else             { CP_WAIT(0); }
        __syncthreads();

        const uint32_t bA = sb + buf * G2_BUF;
        const uint32_t bBh = bA + 32768;
        const uint32_t bBl = bA + 49152;

        #pragma unroll
        for (int kk = 0; kk < 4; kk++) {
            const int kb = kk * 32;
            uint32_t a4[2][4], bh[8][2], bl[8][2];
            #pragma unroll
            for (int mt = 0; mt < 2; mt++) {
                int row = wm * 32 + mt * 16 + (g8 & 1) * 8 + rg;
                ldsm_x4(a4[mt], bA + SWZ128(row * 128 + kb + (g8 >> 1) * 16));
            }
            #pragma unroll
            for (int p = 0; p < 4; p++) {
                int rowb = wn * 64 + p * 16 + (g8 >> 1) * 8 + rg;
                uint32_t off = SWZ128(rowb * 128 + kb + (g8 & 1) * 16);
                uint32_t t[4];
                ldsm_x4(t, bBh + off);
                bh[2 * p][0] = t[0]; bh[2 * p][1] = t[1];
                bh[2 * p + 1][0] = t[2]; bh[2 * p + 1][1] = t[3];
                ldsm_x4(t, bBl + off);
                bl[2 * p][0] = t[0]; bl[2 * p][1] = t[1];
                bl[2 * p + 1][0] = t[2]; bl[2 * p + 1][1] = t[3];
            }
            #pragma unroll
            for (int mt = 0; mt < 2; mt++)
                #pragma unroll
                for (int nt = 0; nt < 8; nt++) {
                    mma16816h(acc[mt][nt], a4[mt], bh[nt]);
                    mma16816h(acc[mt][nt], a4[mt], bl[nt]);
                }
        }
        __syncthreads();
    }

    #pragma unroll
    for (int mt = 0; mt < 2; mt++) {
        int row = m0 + wm * 32 + mt * 16 + (lane >> 2);
        #pragma unroll
        for (int nt = 0; nt < 8; nt++) {
            int col = n0 + wn * 64 + nt * 8 + (lane & 3) * 2;
            if (col < Ntot) {
                float b0 = bias[col], b1 = bias[col + 1];
                float2 v0 = make_float2(acc[mt][nt][0] + b0, acc[mt][nt][1] + b1);
                float2 v1 = make_float2(acc[mt][nt][2] + b0, acc[mt][nt][3] + b1);
                *(float2*)&C[(size_t)row * Ntot + col] = v0;
                *(float2*)&C[(size_t)(row + 8) * Ntot + col] = v1;
            }
        }
    }
}

// =========================================================================
// persistent LSTM recurrence, fp16 2-term, triple-buffered A (1 sync/chunk).
// 128 CTAs x 256 threads; CTA b owns gate rows n0 = b*16 (d in [b*4,b*4+4)).
// smem: W0 64K | W1 64K | A 3x16K | gates 8K = 184K
// =========================================================================
#define PSM_W0 0
#define PSM_W1 65536
#define PSM_A  131072
#define PSM_G  180224
#define PERS_SMEM 188416

__global__ __launch_bounds__(256) void lstm_persistent_kernel(
    const __half* __restrict__ Wc0hi, const __half* __restrict__ Wc0lo,
    const __half* __restrict__ Wc1hi, const __half* __restrict__ Wc1lo,
    __half* __restrict__ h0fA, __half* __restrict__ h0fB,
    const __half* __restrict__ h1zf, __half* __restrict__ H1f,
    const float* __restrict__ bias0, const float* __restrict__ bias0f,
    const float* __restrict__ bias1)
{
    extern __shared__ char smem[];
    const uint32_t sb = smem_u32(smem);
    float* gates = (float*)(smem + PSM_G);
    const int tid = threadIdx.x, wid = tid >> 5, lane = tid & 31;
    const int n0 = blockIdx.x * 16;
    const int g8 = lane >> 3, rg = lane & 7;

    // persistent weight slices (both layers, hi+lo)
    {
        const __half* srcs[4] = {Wc0hi, Wc0lo, Wc1hi, Wc1lo};
        const uint32_t dsts[4] = {PSM_W0, PSM_W0 + 32768, PSM_W1, PSM_W1 + 32768};
        #pragma unroll
        for (int w = 0; w < 4; w++) {
            const __half* src = srcs[w];
            #pragma unroll
            for (int it = 0; it < 8; it++) {
                int i = it * 256 + tid;
                int ch = i >> 7, r = (i >> 3) & 15, c16 = i & 7;
                cp_async16(sb + dsts[w] + ch * 2048 + SWZ128(r * 128 + c16 * 16),
                           src + (size_t)(n0 + r) * 1024 + ch * 64 + c16 * 8, 16);
            }
        }
        CP_COMMIT();
    }

    float rb0[2][4], rb0f[2][4], rb1[2][4];
    #pragma unroll
    for (int it = 0; it < 2; it++) {
        int idx = it * 256 + tid;
        int dd = idx & 3;
        int d = blockIdx.x * 4 + dd;
        #pragma unroll
        for (int gte = 0; gte < 4; gte++) {
            rb0[it][gte]  = bias0[gte * 512 + d];
            rb0f[it][gte] = bias0f[gte * 512 + d];
            rb1[it][gte]  = bias1[gte * 512 + d];
        }
    }

    float c0r[2] = {0.f, 0.f}, c1r[2] = {0.f, 0.f};
    unsigned epoch = 0;
    int cur = 0;

    for (int t = 0; t < TT; t++) {
        #pragma unroll
        for (int layer = 0; layer < 2; layer++) {
            const __half *xf, *hf;
            int kstart;
            if (layer == 0) {
                kstart = (t == 0) ? 8 : 0;
                xf = (t == 0) ? (const __half*)0 : H1f + (size_t)(t - 1) * BB * DD;
                hf = cur ? h0fB : h0fA;
            } else {
                kstart = 0;
                xf = cur ? h0fA : h0fB;     // newly written h0
                hf = (t == 0) ? h1zf : H1f + (size_t)(t - 1) * BB * DD;
            }
            const uint32_t wbase = sb + (layer ? PSM_W1 : PSM_W0);

            auto load_chunk = [&](int ch, int buf) {
                const __half* src = (ch < 8) ? xf : hf;
                int koff = (ch & 7) * 64;
                const uint32_t base = sb + PSM_A + buf * 16384;
                #pragma unroll
                for (int it = 0; it < 4; it++) {
                    int i = it * 256 + tid;
                    int r = i >> 3, c16 = i & 7;
                    cp_async16(base + SWZ128(r * 128 + c16 * 16),
                               src + (size_t)r * 512 + koff + c16 * 8, 16);
                }
                CP_COMMIT();
            };

            float acc[2][4];
            #pragma unroll
            for (int b = 0; b < 2; b++)
                #pragma unroll
                for (int j = 0; j < 4; j++) acc[b][j] = 0.f;

            // triple-buffer, single sync per chunk
            load_chunk(kstart, 0);
            if (kstart + 1 < 16) load_chunk(kstart + 1, 1);
            for (int ch = kstart; ch < 16; ch++) {
                const int i = ch - kstart;
                if (ch + 1 < 16) { CP_WAIT(1); }
                else             { CP_WAIT(0); }
                __syncthreads();
                if (ch + 2 < 16) load_chunk(ch + 2, (i + 2) % 3);

                const uint32_t bA = sb + PSM_A + (i % 3) * 16384;
                const uint32_t bW = wbase + ch * 2048;
                const uint32_t bWl = bW + 32768;

                #pragma unroll
                for (int kk = 0; kk < 4; kk++) {
                    const int kb = kk * 32;
                    uint32_t a4[4], tw[4], twl[4];
                    int row = wid * 16 + (g8 & 1) * 8 + rg;
                    ldsm_x4(a4, bA + SWZ128(row * 128 + kb + (g8 >> 1) * 16));
                    int rowb = (g8 >> 1) * 8 + rg;
                    uint32_t offB = SWZ128(rowb * 128 + kb + (g8 & 1) * 16);
                    ldsm_x4(tw, bW + offB);
                    ldsm_x4(twl, bWl + offB);
                    uint32_t bh0[2] = {tw[0], tw[1]},  bh1[2] = {tw[2], tw[3]};
                    uint32_t bl0[2] = {twl[0], twl[1]}, bl1[2] = {twl[2], twl[3]};
                    mma16816h(acc[0], a4, bh0);
                    mma16816h(acc[0], a4, bl0);
                    mma16816h(acc[1], a4, bh1);
                    mma16816h(acc[1], a4, bl1);
                }
            }
            __syncthreads();

            {
                int r0 = wid * 16 + (lane >> 2);
                int cb = (lane & 3) * 2;
                #pragma unroll
                for (int b = 0; b < 2; b++) {
                    gates[r0 * 16 + b * 8 + cb]           = acc[b][0];
                    gates[r0 * 16 + b * 8 + cb + 1]       = acc[b][1];
                    gates[(r0 + 8) * 16 + b * 8 + cb]     = acc[b][2];
                    gates[(r0 + 8) * 16 + b * 8 + cb + 1] = acc[b][3];
                }
            }
            __syncthreads();

            __half* of = (layer == 0) ? (cur ? h0fA : h0fB) : (H1f + (size_t)t * BB * DD);
            #pragma unroll
            for (int it = 0; it < 2; it++) {
                int idx = it * 256 + tid;
                int row = idx >> 2, dd = idx & 3;
                int d = blockIdx.x * 4 + dd;
                const float* rb = (layer == 0) ? ((t == 0) ? rb0[it] : rb0f[it]) : rb1[it];
                float gi = gates[row * 16 + dd * 4 + 0] + rb[0];
                float gf = gates[row * 16 + dd * 4 + 1] + rb[1];
                float gg = gates[row * 16 + dd * 4 + 2] + rb[2];
                float go = gates[row * 16 + dd * 4 + 3] + rb[3];
                float i_ = 1.f / (1.f + expf(-gi));
                float f_ = 1.f / (1.f + expf(-gf));
                float g_ = tanhf(gg);
                float o_ = 1.f / (1.f + expf(-go));
                float* cr = (layer == 0) ? &c0r[it] : &c1r[it];
                float cn = f_ * (*cr) + i_ * g_;
                *cr = cn;
                of[row * 512 + d] = __float2half_rn(o_ * tanhf(cn));
            }

            __threadfence();
            __syncthreads();
            epoch++;
            if (tid == 0) {
                atomicAdd(&g_bar, 1u);
                unsigned target = epoch * NCTA;
                volatile unsigned* p = &g_bar;
                while (*p < target) { }
                __threadfence();
            }
            __syncthreads();
        }
        cur ^= 1;
    }
}

// =========================================================================
// host
// =========================================================================
extern "C" void kernel_launch(void* const* d_in, const int* in_sizes, int n_in,
                              void* d_out, int out_size) {
    const float* input_ = (const float*)d_in[0];
    const float* W_ih0  = (const float*)d_in[1];
    const float* W_hh0  = (const float*)d_in[2];
    const float* b_ih0  = (const float*)d_in[3];
    const float* b_hh0  = (const float*)d_in[4];
    const float* W_ih1  = (const float*)d_in[5];
    const float* W_hh1  = (const float*)d_in[6];
    const float* b_ih1  = (const float*)d_in[7];
    const float* b_hh1  = (const float*)d_in[8];
    const float* W_enc  = (const float*)d_in[9];
    const float* b_enc  = (const float*)d_in[10];
    float* out = (float*)d_out;

    float *p_Mtmp, *p_bias0, *p_bias0f, *p_bias1;
    __half *p_A1f, *p_B1fhi, *p_B1flo, *p_B2fhi, *p_B2flo;
    __half *p_H1f, *p_h0fA, *p_h0fB, *p_h1zf;
    __half *p_Wc0hi, *p_Wc0lo, *p_Wc1hi, *p_Wc1lo;
    cudaGetSymbolAddress((void**)&p_Mtmp,   g_Mtmp);
    cudaGetSymbolAddress((void**)&p_bias0,  g_bias0);
    cudaGetSymbolAddress((void**)&p_bias0f, g_bias0f);
    cudaGetSymbolAddress((void**)&p_bias1,  g_bias1);
    cudaGetSymbolAddress((void**)&p_A1f,    g_A1f);
    cudaGetSymbolAddress((void**)&p_B1fhi,  g_B1fhi);
    cudaGetSymbolAddress((void**)&p_B1flo,  g_B1flo);
    cudaGetSymbolAddress((void**)&p_B2fhi,  g_B2fhi);
    cudaGetSymbolAddress((void**)&p_B2flo,  g_B2flo);
    cudaGetSymbolAddress((void**)&p_H1f,    g_H1f);
    cudaGetSymbolAddress((void**)&p_h0fA,   g_h0fA);
    cudaGetSymbolAddress((void**)&p_h0fB,   g_h0fB);
    cudaGetSymbolAddress((void**)&p_h1zf,   g_h1zf);
    cudaGetSymbolAddress((void**)&p_Wc0hi,  g_Wc0hi);
    cudaGetSymbolAddress((void**)&p_Wc0lo,  g_Wc0lo);
    cudaGetSymbolAddress((void**)&p_Wc1hi,  g_Wc1hi);
    cudaGetSymbolAddress((void**)&p_Wc1lo,  g_Wc1lo);

    cudaFuncSetAttribute((const void*)gemm1_f16x2_kernel,
                         cudaFuncAttributeMaxDynamicSharedMemorySize, G1_SMEM);
    cudaFuncSetAttribute((const void*)gemm_f16x2_kernel,
                         cudaFuncAttributeMaxDynamicSharedMemorySize, G2_SMEM);
    cudaFuncSetAttribute((const void*)lstm_persistent_kernel,
                         cudaFuncAttributeMaxDynamicSharedMemorySize, PERS_SMEM);

    // ---- prep ----
    prep_misc_kernel<<<(BB * DD + 255) / 256, 256>>>(input_, b_ih0, b_hh0, b_ih1, b_hh1);
    cudaMemsetAsync(p_Mtmp, 0, (size_t)GG * DD * sizeof(float));
    bfused_kernel<<<GG, 256>>>(W_ih0, b_enc);

    dim3 tb(32, 8);
    transpose_split_f16_kernel<<<dim3(DD / 32, (VV + 31) / 32), tb>>>(W_enc, p_B1fhi, p_B1flo);
    f32_to_f16_kernel<<<(GG * VV / 4 + 255) / 256, 256>>>(W_ih0, p_A1f, GG * VV);
    split_f16_kernel<<<(VV * DD / 4 + 255) / 256, 256>>>(W_enc, p_B2fhi, p_B2flo, VV * DD);

    // GEMM1: Mtmp += W_ih0 @ W_enc^T  [fp16 2-term, BM=128, split-K=2, 128 CTAs]
    gemm1_f16x2_kernel<<<dim3(DD / 128, GG / 128, 2), 256, G1_SMEM>>>(
        p_A1f, p_B1fhi, p_B1flo, p_Mtmp);

    // fused, gate-interleaved fp16 cell weights
    build_cell_w_kernel<<<2048, 256>>>(p_Mtmp, W_hh0, p_Wc0hi, p_Wc0lo);
    build_cell_w_kernel<<<2048, 256>>>(W_ih1, W_hh1, p_Wc1hi, p_Wc1lo);

    // ---- recurrence: one persistent launch ----
    lstm_persistent_kernel<<<NCTA, 256, PERS_SMEM>>>(
        p_Wc0hi, p_Wc0lo, p_Wc1hi, p_Wc1lo,
        p_h0fA, p_h0fB, p_h1zf, p_H1f,
        p_bias0, p_bias0f, p_bias1);

    // GEMM2: OUT(2560,10000) = H1f @ (B2hi+B2lo)^T + b_enc  [fp16 2-term]
    gemm_f16x2_kernel<<<dim3((VV + 127) / 128, (TT * BB) / 256), 512, G2_SMEM>>>(
        p_H1f, p_B2fhi, p_B2flo, out, b_enc, TT * BB, VV, DD);
}